// round 1
// baseline (speedup 1.0000x reference)
#include <cuda_runtime.h>
#include <cuda_bf16.h>
#include <cstdint>

#define BB   2
#define SQ   2048
#define DD   1024
#define NH   16
#define HD   64
#define BH   (BB*NH)      // 32
#define NREL 129
#define QRS  132          // qrel row stride (padded)

// ---------------- scratch (device globals: sanctioned workaround) ----------
__device__ float g_q[(size_t)BH * SQ * HD];      // [bh][s][d]
__device__ float g_k[(size_t)BH * SQ * HD];
__device__ float g_v[(size_t)BH * SQ * HD];
__device__ float g_qrel[(size_t)BH * SQ * QRS];  // [bh][q][129 (pad 132)]

// ===========================================================================
// Kernel 1: fused QKV projection. Y = X @ W + b, written in [B,H,S,d] layout.
// Classic 128x128x8 register-blocked SGEMM, 256 threads, 8x8 micro-tile.
// grid: (N/128=8, M/128=32, 3)
// ===========================================================================
__global__ __launch_bounds__(256) void qkv_gemm(
    const float* __restrict__ X,
    const float* __restrict__ Wq, const float* __restrict__ bq,
    const float* __restrict__ Wk, const float* __restrict__ bk,
    const float* __restrict__ Wv, const float* __restrict__ bv)
{
    __shared__ float As[8 * 132];   // [k][m], padded to kill STS conflicts
    __shared__ float Bs[8 * 128];   // [k][n]

    const float* W; const float* bias; float* out;
    if (blockIdx.z == 0)      { W = Wq; bias = bq; out = g_q; }
    else if (blockIdx.z == 1) { W = Wk; bias = bk; out = g_k; }
    else                      { W = Wv; bias = bv; out = g_v; }

    const int tid = threadIdx.x;
    const int tx = tid & 15, ty = tid >> 4;
    const int m0 = blockIdx.y * 128, n0 = blockIdx.x * 128;

    const int arow = tid >> 1;          // 0..127
    const int acol = (tid & 1) * 4;     // 0 or 4
    const int brow = tid >> 5;          // 0..7
    const int bcol = (tid & 31) * 4;    // 0..124

    float acc[8][8];
    #pragma unroll
    for (int i = 0; i < 8; i++)
        #pragma unroll
        for (int j = 0; j < 8; j++) acc[i][j] = 0.f;

    float4 apre = *(const float4*)&X[(size_t)(m0 + arow) * DD + acol];
    float4 bpre = *(const float4*)&W[(size_t)brow * DD + n0 + bcol];

    for (int k0 = 0; k0 < DD; k0 += 8) {
        As[(acol + 0) * 132 + arow] = apre.x;
        As[(acol + 1) * 132 + arow] = apre.y;
        As[(acol + 2) * 132 + arow] = apre.z;
        As[(acol + 3) * 132 + arow] = apre.w;
        *(float4*)&Bs[brow * 128 + bcol] = bpre;
        __syncthreads();

        if (k0 + 8 < DD) {
            apre = *(const float4*)&X[(size_t)(m0 + arow) * DD + k0 + 8 + acol];
            bpre = *(const float4*)&W[(size_t)(k0 + 8 + brow) * DD + n0 + bcol];
        }

        #pragma unroll
        for (int kk = 0; kk < 8; kk++) {
            float a[8], b[8];
            *(float4*)(a)     = *(const float4*)&As[kk * 132 + ty * 4];
            *(float4*)(a + 4) = *(const float4*)&As[kk * 132 + 64 + ty * 4];
            *(float4*)(b)     = *(const float4*)&Bs[kk * 128 + tx * 4];
            *(float4*)(b + 4) = *(const float4*)&Bs[kk * 128 + 64 + tx * 4];
            #pragma unroll
            for (int i = 0; i < 8; i++)
                #pragma unroll
                for (int j = 0; j < 8; j++)
                    acc[i][j] += a[i] * b[j];
        }
        __syncthreads();
    }

    // epilogue: add bias, scatter into [B,H,S,d]
    #pragma unroll
    for (int i = 0; i < 8; i++) {
        const int m = m0 + ty * 4 + ((i < 4) ? i : 60 + i);
        const int bidx = m >> 11;          // /2048
        const int s = m & 2047;
        #pragma unroll
        for (int jg = 0; jg < 2; jg++) {
            const int n = n0 + tx * 4 + jg * 64;
            const int hh = n >> 6, dd = n & 63;
            float4 v;
            v.x = acc[i][jg * 4 + 0] + __ldg(&bias[n + 0]);
            v.y = acc[i][jg * 4 + 1] + __ldg(&bias[n + 1]);
            v.z = acc[i][jg * 4 + 2] + __ldg(&bias[n + 2]);
            v.w = acc[i][jg * 4 + 3] + __ldg(&bias[n + 3]);
            *(float4*)&out[(((size_t)(bidx * NH + hh)) * SQ + s) * HD + dd] = v;
        }
    }
}

// ===========================================================================
// Kernel 2: qrel[bh][q][r] = Q[bh][q][:] . emb_k[r][:]   (r in [0,129))
// grid: (S/16=128, BH=32), 128 threads
// ===========================================================================
__global__ __launch_bounds__(128) void qrel_kernel(const float* __restrict__ emb_k)
{
    __shared__ float ek[NREL * 68];
    const int tid = threadIdx.x;
    const int bh = blockIdx.y, q0 = blockIdx.x * 16;

    for (int idx = tid; idx < NREL * 16; idx += 128) {
        const int r = idx >> 4, d4 = (idx & 15) << 2;
        *(float4*)&ek[r * 68 + d4] = *(const float4*)&emb_k[r * HD + d4];
    }

    const int qi = tid >> 3;     // 0..15
    const int rg = tid & 7;
    float4 qreg[16];
    const float* qp = g_q + (size_t)(bh * SQ + q0 + qi) * HD;
    #pragma unroll
    for (int u = 0; u < 16; u++) qreg[u] = *(const float4*)&qp[u * 4];
    __syncthreads();

    float* orow = g_qrel + (size_t)(bh * SQ + q0 + qi) * QRS;
    for (int r = rg; r < NREL; r += 8) {
        const float* er = ek + r * 68;
        float s = 0.f;
        #pragma unroll
        for (int u = 0; u < 16; u++) {
            float4 e = *(const float4*)&er[u * 4];
            s += qreg[u].x * e.x + qreg[u].y * e.y + qreg[u].z * e.z + qreg[u].w * e.w;
        }
        orow[r] = s;
    }
}

// ===========================================================================
// Kernel 3: flash attention with relative-position terms.
// One (bh, 64-row q tile) per block, 256 threads (16x16, 4x4 micro-tile,
// strided column mapping c_j = tx + 16*j for conflict-free smem access).
// Online softmax; pw[64][129] bucket histogram for the relative-V term.
// grid: (S/64=32, BH=32)
// ===========================================================================
#define ATTN_SMEM_FLOATS (4 * 64 * 68 + 64 * QRS + 4 * 64 + 4)
#define ATTN_SMEM_BYTES  (ATTN_SMEM_FLOATS * 4)

__global__ __launch_bounds__(256) void attn_kernel(
    const float* __restrict__ mask,
    const float* __restrict__ emb_v,
    float* __restrict__ out)
{
    extern __shared__ float sm[];
    float* Qs  = sm;                 // 64*68
    float* Ks  = Qs + 64 * 68;       // 64*68
    float* Vs  = Ks + 64 * 68;       // 64*68
    float* Ps  = Vs + 64 * 68;       // 64*68
    float* pw  = Ps + 64 * 68;       // 64*132
    float* m_s  = pw + 64 * QRS;     // 64
    float* l_s  = m_s + 64;          // 64
    float* sc_s = l_s + 64;          // 64
    float* msk  = sc_s + 64;         // 64
    int*   flag = (int*)(msk + 64);

    const int tid = threadIdx.x;
    const int tx = tid & 15, ty = tid >> 4;
    const int bh = blockIdx.y;
    const int b = bh >> 4, h = bh & 15;
    const int q0 = blockIdx.x * 64;
    const int r0 = ty * 4;

    // load Q tile
    {
        const float* qptr = g_q + (size_t)(bh * SQ + q0) * HD;
        for (int idx = tid; idx < 64 * 16; idx += 256) {
            const int r = idx >> 4, d4 = (idx & 15) << 2;
            *(float4*)&Qs[r * 68 + d4] = *(const float4*)&qptr[r * HD + d4];
        }
    }
    for (int idx = tid; idx < 64 * QRS; idx += 256) pw[idx] = 0.f;
    if (tid < 64) { m_s[tid] = -1e30f; l_s[tid] = 0.f; }
    if (tid == 0) *flag = 0;

    float acc[4][4];
    #pragma unroll
    for (int i = 0; i < 4; i++)
        #pragma unroll
        for (int j = 0; j < 4; j++) acc[i][j] = 0.f;

    const float* qrl = g_qrel + (size_t)bh * SQ * QRS;

    __syncthreads();

    for (int k0 = 0; k0 < SQ; k0 += 64) {
        // ---- load K/V tiles + mask; clear flag for this iteration ----
        {
            const float* kptr = g_k + (size_t)(bh * SQ + k0) * HD;
            const float* vptr = g_v + (size_t)(bh * SQ + k0) * HD;
            for (int idx = tid; idx < 64 * 16; idx += 256) {
                const int r = idx >> 4, d4 = (idx & 15) << 2;
                *(float4*)&Ks[r * 68 + d4] = *(const float4*)&kptr[r * HD + d4];
                *(float4*)&Vs[r * 68 + d4] = *(const float4*)&vptr[r * HD + d4];
            }
            if (tid < 64) msk[tid] = mask[b * SQ + k0 + tid];
            if (tid == 0) *flag = 0;
        }
        __syncthreads();   // S1

        // ---- scores + online softmax ----
        float p[4][4], sc[4];
        {
            float sr[4][4];
            #pragma unroll
            for (int i = 0; i < 4; i++)
                #pragma unroll
                for (int j = 0; j < 4; j++) sr[i][j] = 0.f;

            #pragma unroll
            for (int d = 0; d < HD; d += 4) {
                float4 qa[4], kb[4];
                #pragma unroll
                for (int i = 0; i < 4; i++) qa[i] = *(const float4*)&Qs[(r0 + i) * 68 + d];
                #pragma unroll
                for (int j = 0; j < 4; j++) kb[j] = *(const float4*)&Ks[(tx + 16 * j) * 68 + d];
                #pragma unroll
                for (int i = 0; i < 4; i++)
                    #pragma unroll
                    for (int j = 0; j < 4; j++)
                        sr[i][j] += qa[i].x * kb[j].x + qa[i].y * kb[j].y
                                  + qa[i].z * kb[j].z + qa[i].w * kb[j].w;
            }

            // relative-key bias + mask + scale
            #pragma unroll
            for (int i = 0; i < 4; i++) {
                const int q = q0 + r0 + i;
                const float* qr = qrl + (size_t)q * QRS;
                #pragma unroll
                for (int j = 0; j < 4; j++) {
                    const int k = k0 + tx + 16 * j;
                    int bkt = q - k;
                    bkt = min(max(bkt, -64), 64) + 64;
                    sr[i][j] = (sr[i][j] + __ldg(&qr[bkt])) * 0.125f + msk[tx + 16 * j];
                }
            }

            float newm[4], rs[4];
            #pragma unroll
            for (int i = 0; i < 4; i++) {
                float mx = fmaxf(fmaxf(sr[i][0], sr[i][1]), fmaxf(sr[i][2], sr[i][3]));
                #pragma unroll
                for (int o = 1; o < 16; o <<= 1)
                    mx = fmaxf(mx, __shfl_xor_sync(0xffffffffu, mx, o));
                const float om = m_s[r0 + i];
                newm[i] = fmaxf(om, mx);
                sc[i] = __expf(om - newm[i]);
                float sum = 0.f;
                #pragma unroll
                for (int j = 0; j < 4; j++) {
                    p[i][j] = __expf(sr[i][j] - newm[i]);
                    sum += p[i][j];
                }
                #pragma unroll
                for (int o = 1; o < 16; o <<= 1)
                    sum += __shfl_xor_sync(0xffffffffu, sum, o);
                rs[i] = sum;
            }
            if (tx == 0) {
                #pragma unroll
                for (int i = 0; i < 4; i++) {
                    l_s[r0 + i] = l_s[r0 + i] * sc[i] + rs[i];
                    m_s[r0 + i] = newm[i];
                    sc_s[r0 + i] = sc[i];
                    if (sc[i] < 1.f) *flag = 1;
                }
            }
            // stash P, rescale register accumulator
            #pragma unroll
            for (int i = 0; i < 4; i++) {
                #pragma unroll
                for (int j = 0; j < 4; j++) {
                    Ps[(r0 + i) * 68 + tx + 16 * j] = p[i][j];
                    acc[i][j] *= sc[i];
                }
            }
        }
        __syncthreads();   // S2: Ps / l / sc / flag visible

        // ---- rescale pw histogram if any row's max moved ----
        if (*flag) {
            const int row = tid >> 2, rr = tid & 3;
            const float s = sc_s[row];
            float* pr = pw + row * QRS;
            for (int r = rr; r < NREL; r += 4) pr[r] *= s;
        }
        __syncthreads();   // S3: pw rescale done before accumulation

        // ---- accumulate relative-V bucket histogram ----
        {
            const int prow = tid >> 2, pp = tid & 3;
            const int base = q0 + prow - (k0 + pp * 16) + 64;
            float s0 = 0.f, s128 = 0.f;
            float* pwrow = pw + prow * QRS;
            const float* psrow = Ps + prow * 68 + pp * 16;
            #pragma unroll
            for (int t2 = 0; t2 < 16; t2++) {
                const float pv = psrow[t2];
                const int bkt = base - t2;
                if (bkt <= 0)        s0 += pv;
                else if (bkt >= 128) s128 += pv;
                else                 pwrow[bkt] += pv;   // unique (row,bkt) owner
            }
            if (s0 != 0.f)   atomicAdd(&pwrow[0], s0);
            if (s128 != 0.f) atomicAdd(&pwrow[128], s128);
        }

        // ---- acc += P @ V ----
        #pragma unroll
        for (int kk = 0; kk < 64; kk += 4) {
            float4 pr4[4];
            #pragma unroll
            for (int i = 0; i < 4; i++) pr4[i] = *(const float4*)&Ps[(r0 + i) * 68 + kk];
            #pragma unroll
            for (int u = 0; u < 4; u++) {
                float vv[4];
                #pragma unroll
                for (int j = 0; j < 4; j++) vv[j] = Vs[(kk + u) * 68 + tx + 16 * j];
                const float* pf = (const float*)&pr4[0];
                #pragma unroll
                for (int i = 0; i < 4; i++) {
                    const float pe = ((const float*)&pr4[i])[u];
                    #pragma unroll
                    for (int j = 0; j < 4; j++) acc[i][j] += pe * vv[j];
                }
                (void)pf;
            }
        }
        __syncthreads();   // S4: tile fully consumed
    }

    // ---- epilogue: ctx = (acc + pw @ emb_v) / l ----
    {
        // reuse K/V smem for emb_v (129*64 floats fit in 2*64*68)
        float* evs = Ks;
        for (int idx = tid; idx < NREL * HD; idx += 256) evs[idx] = emb_v[idx];
    }
    __syncthreads();

    float rl[4];
    #pragma unroll
    for (int i = 0; i < 4; i++) rl[i] = 1.f / l_s[r0 + i];

    const float* evs = Ks;
    for (int r = 0; r < NREL; r++) {
        float ev[4];
        #pragma unroll
        for (int j = 0; j < 4; j++) ev[j] = evs[r * HD + tx + 16 * j];
        #pragma unroll
        for (int i = 0; i < 4; i++) {
            const float pv = pw[(r0 + i) * QRS + r];
            #pragma unroll
            for (int j = 0; j < 4; j++) acc[i][j] += pv * ev[j];
        }
    }

    #pragma unroll
    for (int i = 0; i < 4; i++) {
        const int q = q0 + r0 + i;
        float* op = out + ((size_t)(b * SQ + q)) * DD + h * HD;
        #pragma unroll
        for (int j = 0; j < 4; j++)
            op[tx + 16 * j] = acc[i][j] * rl[i];
    }
}

// ===========================================================================
extern "C" void kernel_launch(void* const* d_in, const int* in_sizes, int n_in,
                              void* d_out, int out_size)
{
    const float* hidden = (const float*)d_in[0];
    const float* mask   = (const float*)d_in[1];
    const float* Wq     = (const float*)d_in[2];
    const float* bq     = (const float*)d_in[3];
    const float* Wk     = (const float*)d_in[4];
    const float* bk     = (const float*)d_in[5];
    const float* Wv     = (const float*)d_in[6];
    const float* bv     = (const float*)d_in[7];
    const float* emb_k  = (const float*)d_in[8];
    const float* emb_v  = (const float*)d_in[9];
    float* out = (float*)d_out;

    dim3 g1(DD / 128, (BB * SQ) / 128, 3);
    qkv_gemm<<<g1, 256>>>(hidden, Wq, bq, Wk, bk, Wv, bv);

    dim3 g2(SQ / 16, BH);
    qrel_kernel<<<g2, 128>>>(emb_k);

    cudaFuncSetAttribute(attn_kernel, cudaFuncAttributeMaxDynamicSharedMemorySize,
                         ATTN_SMEM_BYTES);
    dim3 g3(SQ / 64, BH);
    attn_kernel<<<g3, 256, ATTN_SMEM_BYTES>>>(mask, emb_v, out);
}

// round 2
// speedup vs baseline: 1.4481x; 1.4481x over previous
#include <cuda_runtime.h>
#include <cuda_bf16.h>
#include <cstdint>

#define BB   2
#define SQ   2048
#define DD   1024
#define NH   16
#define HD   64
#define BH   (BB*NH)      // 32
#define NREL 129
#define QRS  132          // qrel row stride (padded)

// ---------------- scratch (device globals: sanctioned workaround) ----------
__device__ float g_q[(size_t)BH * SQ * HD];      // [bh][s][d]  (tf32-rounded)
__device__ float g_k[(size_t)BH * SQ * HD];
__device__ float g_v[(size_t)BH * SQ * HD];
__device__ float g_qrel[(size_t)BH * SQ * QRS];  // [bh][q][129 (pad 132)]

// ---------------- tf32 helpers --------------------------------------------
__device__ __forceinline__ float tf32r(float x) {
    uint32_t u; asm("cvt.rna.tf32.f32 %0, %1;" : "=r"(u) : "f"(x));
    return __uint_as_float(u);
}
__device__ __forceinline__ void mma8(float4& d,
                                     uint32_t a0, uint32_t a1, uint32_t a2, uint32_t a3,
                                     uint32_t b0, uint32_t b1) {
    asm("mma.sync.aligned.m16n8k8.row.col.f32.tf32.tf32.f32 "
        "{%0,%1,%2,%3},{%4,%5,%6,%7},{%8,%9},{%0,%1,%2,%3};"
        : "+f"(d.x), "+f"(d.y), "+f"(d.z), "+f"(d.w)
        : "r"(a0), "r"(a1), "r"(a2), "r"(a3), "r"(b0), "r"(b1));
}

// ===========================================================================
// Kernel 1: fused QKV projection via tf32 mma. Y = X @ W + b -> [B,H,S,d].
// 128x128x16 tile, 256 threads, 8 warps as 4(m) x 2(n), warp tile 32x64.
// grid: (8, 32, 3)
// ===========================================================================
__global__ __launch_bounds__(256) void qkv_gemm(
    const float* __restrict__ X,
    const float* __restrict__ Wq, const float* __restrict__ bq,
    const float* __restrict__ Wk, const float* __restrict__ bk,
    const float* __restrict__ Wv, const float* __restrict__ bv)
{
    __shared__ float As[16 * 136];   // [k][m], stride 136 -> conflict-free frags
    __shared__ float Bs[16 * 136];   // [k][n]

    const float* W; const float* bias; float* out;
    if (blockIdx.z == 0)      { W = Wq; bias = bq; out = g_q; }
    else if (blockIdx.z == 1) { W = Wk; bias = bk; out = g_k; }
    else                      { W = Wv; bias = bv; out = g_v; }

    const int tid = threadIdx.x;
    const int wid = tid >> 5, lane = tid & 31, lr = lane >> 2, lc = lane & 3;
    const int wm = wid >> 1, wn = wid & 1;
    const int m0 = blockIdx.y * 128, n0 = blockIdx.x * 128;

    const int arow = tid >> 1, acol = (tid & 1) * 8;
    const int brow = tid >> 4, bcol = (tid & 15) * 8;

    float4 acc[2][8];
    #pragma unroll
    for (int mt = 0; mt < 2; mt++)
        #pragma unroll
        for (int nt = 0; nt < 8; nt++) acc[mt][nt] = make_float4(0.f, 0.f, 0.f, 0.f);

    const float* xp = X + (size_t)(m0 + arow) * DD + acol;
    const float* wp = W + (size_t)brow * DD + n0 + bcol;
    float4 xa0 = *(const float4*)(xp);
    float4 xa1 = *(const float4*)(xp + 4);
    float4 wb0 = *(const float4*)(wp);
    float4 wb1 = *(const float4*)(wp + 4);

    uint32_t* Asu = (uint32_t*)As;
    uint32_t* Bsu = (uint32_t*)Bs;

    for (int k0 = 0; k0 < DD; k0 += 16) {
        As[(acol + 0) * 136 + arow] = tf32r(xa0.x);
        As[(acol + 1) * 136 + arow] = tf32r(xa0.y);
        As[(acol + 2) * 136 + arow] = tf32r(xa0.z);
        As[(acol + 3) * 136 + arow] = tf32r(xa0.w);
        As[(acol + 4) * 136 + arow] = tf32r(xa1.x);
        As[(acol + 5) * 136 + arow] = tf32r(xa1.y);
        As[(acol + 6) * 136 + arow] = tf32r(xa1.z);
        As[(acol + 7) * 136 + arow] = tf32r(xa1.w);
        {
            float4 t0 = make_float4(tf32r(wb0.x), tf32r(wb0.y), tf32r(wb0.z), tf32r(wb0.w));
            float4 t1 = make_float4(tf32r(wb1.x), tf32r(wb1.y), tf32r(wb1.z), tf32r(wb1.w));
            *(float4*)&Bs[brow * 136 + bcol]     = t0;
            *(float4*)&Bs[brow * 136 + bcol + 4] = t1;
        }
        __syncthreads();

        if (k0 + 16 < DD) {
            xa0 = *(const float4*)(xp + k0 + 16);
            xa1 = *(const float4*)(xp + k0 + 20);
            wb0 = *(const float4*)(wp + (size_t)(k0 + 16) * DD);
            wb1 = *(const float4*)(wp + (size_t)(k0 + 16) * DD + 4);
        }

        #pragma unroll
        for (int kc = 0; kc < 16; kc += 8) {
            uint32_t a[2][4];
            #pragma unroll
            for (int mt = 0; mt < 2; mt++) {
                const int mb = wm * 32 + mt * 16;
                a[mt][0] = Asu[(kc + lc)     * 136 + mb + lr];
                a[mt][1] = Asu[(kc + lc)     * 136 + mb + lr + 8];
                a[mt][2] = Asu[(kc + lc + 4) * 136 + mb + lr];
                a[mt][3] = Asu[(kc + lc + 4) * 136 + mb + lr + 8];
            }
            #pragma unroll
            for (int nt = 0; nt < 8; nt++) {
                const int nb = wn * 64 + nt * 8;
                uint32_t b0 = Bsu[(kc + lc)     * 136 + nb + lr];
                uint32_t b1 = Bsu[(kc + lc + 4) * 136 + nb + lr];
                mma8(acc[0][nt], a[0][0], a[0][1], a[0][2], a[0][3], b0, b1);
                mma8(acc[1][nt], a[1][0], a[1][1], a[1][2], a[1][3], b0, b1);
            }
        }
        __syncthreads();
    }

    // epilogue: add bias, scatter into [B,H,S,d]
    #pragma unroll
    for (int mt = 0; mt < 2; mt++) {
        const int mA = m0 + wm * 32 + mt * 16 + lr;
        const int mB = mA + 8;
        #pragma unroll
        for (int nt = 0; nt < 8; nt++) {
            const int n = n0 + wn * 64 + nt * 8 + 2 * lc;
            const float b0v = __ldg(&bias[n]), b1v = __ldg(&bias[n + 1]);
            const int hh = n >> 6, dd = n & 63;
            {
                const int bidx = mA >> 11, s = mA & 2047;
                float2 v; v.x = acc[mt][nt].x + b0v; v.y = acc[mt][nt].y + b1v;
                *(float2*)&out[(((size_t)(bidx * NH + hh)) * SQ + s) * HD + dd] = v;
            }
            {
                const int bidx = mB >> 11, s = mB & 2047;
                float2 v; v.x = acc[mt][nt].z + b0v; v.y = acc[mt][nt].w + b1v;
                *(float2*)&out[(((size_t)(bidx * NH + hh)) * SQ + s) * HD + dd] = v;
            }
        }
    }
}

// ===========================================================================
// Kernel 2: qrel[bh][q][r] = Q[bh][q][:] . emb_k[r][:]  (fp32, tiny)
// grid: (S/16=128, BH=32), 128 threads
// ===========================================================================
__global__ __launch_bounds__(128) void qrel_kernel(const float* __restrict__ emb_k)
{
    __shared__ float ek[NREL * 68];
    const int tid = threadIdx.x;
    const int bh = blockIdx.y, q0 = blockIdx.x * 16;

    for (int idx = tid; idx < NREL * 16; idx += 128) {
        const int r = idx >> 4, d4 = (idx & 15) << 2;
        *(float4*)&ek[r * 68 + d4] = *(const float4*)&emb_k[r * HD + d4];
    }

    const int qi = tid >> 3;
    const int rg = tid & 7;
    float4 qreg[16];
    const float* qp = g_q + (size_t)(bh * SQ + q0 + qi) * HD;
    #pragma unroll
    for (int u = 0; u < 16; u++) qreg[u] = *(const float4*)&qp[u * 4];
    __syncthreads();

    float* orow = g_qrel + (size_t)(bh * SQ + q0 + qi) * QRS;
    for (int r = rg; r < NREL; r += 8) {
        const float* er = ek + r * 68;
        float s = 0.f;
        #pragma unroll
        for (int u = 0; u < 16; u++) {
            float4 e = *(const float4*)&er[u * 4];
            s += qreg[u].x * e.x + qreg[u].y * e.y + qreg[u].z * e.z + qreg[u].w * e.w;
        }
        orow[r] = s;
    }
}

// ===========================================================================
// Kernel 3: flash attention via tf32 mma. q-tile 128, k-tile 64, 8 warps,
// each warp owns 16 q-rows (softmax is quad-local; pw histogram quad-private
// in first-tile-max frame -> no per-tile rescale). grid: (16, 32), 256 thr.
// smem (floats): Qs[128*68] Ks[64*68] Vt[64*68] Ps[128*68] qb[128*68]
//                pw[128*136] msk[64]  = 52288 floats = 209152 B
// ===========================================================================
#define ATTN_SMEM_BYTES (52288 * 4)

__global__ __launch_bounds__(256) void attn_tf32(
    const float* __restrict__ mask,
    const float* __restrict__ emb_v,
    float* __restrict__ out)
{
    extern __shared__ float sm[];
    float* Qs  = sm;              // [128][68]
    float* Ks  = sm + 8704;       // [64][68]
    float* Vt  = sm + 13056;      // [64(d)][68] (V transposed)
    float* Ps  = sm + 17408;      // [128][68]
    float* qb  = sm + 26112;      // [128][68]
    float* pw  = sm + 34816;      // [128][136]
    float* msk = sm + 52224;      // [64]
    uint32_t* Qsu = (uint32_t*)Qs;
    uint32_t* Ksu = (uint32_t*)Ks;
    uint32_t* Vtu = (uint32_t*)Vt;
    uint32_t* Psu = (uint32_t*)Ps;

    const int tid = threadIdx.x;
    const int wid = tid >> 5, lane = tid & 31, lr = lane >> 2, lc = lane & 3;
    const int bh = blockIdx.y, b = bh >> 4, h = bh & 15;
    const int q0 = blockIdx.x * 128;
    const int r0w = wid * 16;
    const int rowA = r0w + lr, rowB = rowA + 8;

    // Q tile load (warp-private rows), tf32-rounded once
    {
        const float* qp = g_q + (size_t)(bh * SQ + q0 + r0w) * HD;
        #pragma unroll
        for (int it = 0; it < 8; it++) {
            const int u = lane + 32 * it;
            const int row = u >> 4, c4 = (u & 15) << 2;
            float4 v = *(const float4*)&qp[(size_t)row * HD + c4];
            float* dst = &Qs[(r0w + row) * 68 + c4];
            dst[0] = tf32r(v.x); dst[1] = tf32r(v.y);
            dst[2] = tf32r(v.z); dst[3] = tf32r(v.w);
        }
    }
    for (int i = lane; i < 16 * 136; i += 32) pw[r0w * 136 + i] = 0.f;

    float m_a = -1e30f, m_b = -1e30f, l_a = 0.f, l_b = 0.f;
    float mref_a = -1e30f, mref_b = -1e30f;
    float4 acc[8];
    #pragma unroll
    for (int nt = 0; nt < 8; nt++) acc[nt] = make_float4(0.f, 0.f, 0.f, 0.f);

    const float* qrl = g_qrel + (size_t)bh * SQ * QRS;

    for (int k0 = 0; k0 < SQ; k0 += 64) {
        __syncthreads();   // prior tile fully consumed before overwrite
        // ---- load K (row-major) + V (transposed) tf32-rounded, mask ----
        {
            const int row = tid >> 2, cb = (tid & 3) * 16;
            const float* kp = g_k + (size_t)(bh * SQ + k0 + row) * HD + cb;
            const float* vp = g_v + (size_t)(bh * SQ + k0 + row) * HD + cb;
            #pragma unroll
            for (int u = 0; u < 4; u++) {
                float4 kv = *(const float4*)(kp + u * 4);
                float* kd = &Ks[row * 68 + cb + u * 4];
                kd[0] = tf32r(kv.x); kd[1] = tf32r(kv.y);
                kd[2] = tf32r(kv.z); kd[3] = tf32r(kv.w);
                float4 vv = *(const float4*)(vp + u * 4);
                Vt[(cb + u * 4 + 0) * 68 + row] = tf32r(vv.x);
                Vt[(cb + u * 4 + 1) * 68 + row] = tf32r(vv.y);
                Vt[(cb + u * 4 + 2) * 68 + row] = tf32r(vv.z);
                Vt[(cb + u * 4 + 3) * 68 + row] = tf32r(vv.w);
            }
        }
        if (tid < 64) msk[tid] = mask[(size_t)b * SQ + k0 + tid];
        const int delta = q0 - k0 + 64;
        // ---- stage rel-key bias window qb[row][c] (warp-private rows) ----
        #pragma unroll 4
        for (int i = 0; i < 16; i++) {
            const int row = r0w + i;
            const float* qr = qrl + (size_t)(q0 + row) * QRS;
            #pragma unroll
            for (int half = 0; half < 2; half++) {
                const int cc = lane + 32 * half;
                int bkt = row + delta - cc;
                bkt = min(max(bkt, 0), 128);
                qb[row * 68 + cc] = qr[bkt];
            }
        }
        __syncthreads();

        // ---- scores: S = Q K^T (tf32 mma) ----
        float4 sc4[8];
        #pragma unroll
        for (int nt = 0; nt < 8; nt++) sc4[nt] = make_float4(0.f, 0.f, 0.f, 0.f);
        #pragma unroll
        for (int kc = 0; kc < 64; kc += 8) {
            uint32_t a0 = Qsu[rowA * 68 + kc + lc];
            uint32_t a1 = Qsu[(rowA + 8) * 68 + kc + lc];
            uint32_t a2 = Qsu[rowA * 68 + kc + lc + 4];
            uint32_t a3 = Qsu[(rowA + 8) * 68 + kc + lc + 4];
            #pragma unroll
            for (int nt = 0; nt < 8; nt++) {
                uint32_t b0 = Ksu[(nt * 8 + lr) * 68 + kc + lc];
                uint32_t b1 = Ksu[(nt * 8 + lr) * 68 + kc + lc + 4];
                mma8(sc4[nt], a0, a1, a2, a3, b0, b1);
            }
        }
        // ---- bias + mask + scale ----
        #pragma unroll
        for (int nt = 0; nt < 8; nt++) {
            const int c0 = nt * 8 + 2 * lc;
            float2 qA = *(const float2*)&qb[rowA * 68 + c0];
            float2 qB = *(const float2*)&qb[rowB * 68 + c0];
            float2 mk = *(const float2*)&msk[c0];
            sc4[nt].x = (sc4[nt].x + qA.x) * 0.125f + mk.x;
            sc4[nt].y = (sc4[nt].y + qA.y) * 0.125f + mk.y;
            sc4[nt].z = (sc4[nt].z + qB.x) * 0.125f + mk.x;
            sc4[nt].w = (sc4[nt].w + qB.y) * 0.125f + mk.y;
        }
        // ---- online softmax (quad-local) ----
        float mxA = -1e30f, mxB = -1e30f;
        #pragma unroll
        for (int nt = 0; nt < 8; nt++) {
            mxA = fmaxf(mxA, fmaxf(sc4[nt].x, sc4[nt].y));
            mxB = fmaxf(mxB, fmaxf(sc4[nt].z, sc4[nt].w));
        }
        mxA = fmaxf(mxA, __shfl_xor_sync(0xffffffffu, mxA, 1));
        mxA = fmaxf(mxA, __shfl_xor_sync(0xffffffffu, mxA, 2));
        mxB = fmaxf(mxB, __shfl_xor_sync(0xffffffffu, mxB, 1));
        mxB = fmaxf(mxB, __shfl_xor_sync(0xffffffffu, mxB, 2));
        const float nmA = fmaxf(m_a, mxA), nmB = fmaxf(m_b, mxB);
        const float scA = __expf(m_a - nmA), scB = __expf(m_b - nmB);
        float smA = 0.f, smB = 0.f;
        #pragma unroll
        for (int nt = 0; nt < 8; nt++) {
            sc4[nt].x = __expf(sc4[nt].x - nmA); smA += sc4[nt].x;
            sc4[nt].y = __expf(sc4[nt].y - nmA); smA += sc4[nt].y;
            sc4[nt].z = __expf(sc4[nt].z - nmB); smB += sc4[nt].z;
            sc4[nt].w = __expf(sc4[nt].w - nmB); smB += sc4[nt].w;
        }
        smA += __shfl_xor_sync(0xffffffffu, smA, 1);
        smA += __shfl_xor_sync(0xffffffffu, smA, 2);
        smB += __shfl_xor_sync(0xffffffffu, smB, 1);
        smB += __shfl_xor_sync(0xffffffffu, smB, 2);
        l_a = l_a * scA + smA; m_a = nmA;
        l_b = l_b * scB + smB; m_b = nmB;
        if (mref_a == -1e30f) mref_a = nmA;
        if (mref_b == -1e30f) mref_b = nmB;
        const float fA = __expf(nmA - mref_a);
        const float fB = __expf(nmB - mref_b);
        #pragma unroll
        for (int nt = 0; nt < 8; nt++) {
            acc[nt].x *= scA; acc[nt].y *= scA;
            acc[nt].z *= scB; acc[nt].w *= scB;
        }
        // ---- rel-V histogram, first-tile-max frame (quad-private rows) ----
        float e0A = 0.f, e1A = 0.f, e0B = 0.f, e1B = 0.f;
        #pragma unroll
        for (int nt = 0; nt < 8; nt++) {
            const int c0 = nt * 8 + 2 * lc;
            const int bkA = rowA + delta - c0;
            const int bkB = rowB + delta - c0;
            const float px = sc4[nt].x * fA, py = sc4[nt].y * fA;
            const float pz = sc4[nt].z * fB, pv = sc4[nt].w * fB;
            if (bkA >= 128) e1A += px; else if (bkA <= 0) e0A += px; else pw[rowA * 136 + bkA] += px;
            if (bkA - 1 >= 128) e1A += py; else if (bkA - 1 <= 0) e0A += py; else pw[rowA * 136 + bkA - 1] += py;
            if (bkB >= 128) e1B += pz; else if (bkB <= 0) e0B += pz; else pw[rowB * 136 + bkB] += pz;
            if (bkB - 1 >= 128) e1B += pv; else if (bkB - 1 <= 0) e0B += pv; else pw[rowB * 136 + bkB - 1] += pv;
        }
        if (e0A != 0.f) atomicAdd(&pw[rowA * 136 + 0],   e0A);
        if (e1A != 0.f) atomicAdd(&pw[rowA * 136 + 128], e1A);
        if (e0B != 0.f) atomicAdd(&pw[rowB * 136 + 0],   e0B);
        if (e1B != 0.f) atomicAdd(&pw[rowB * 136 + 128], e1B);
        // ---- stash P (tf32) for PV mma ----
        #pragma unroll
        for (int nt = 0; nt < 8; nt++) {
            const int c0 = nt * 8 + 2 * lc;
            float2 pa; pa.x = tf32r(sc4[nt].x); pa.y = tf32r(sc4[nt].y);
            *(float2*)&Ps[rowA * 68 + c0] = pa;
            float2 pb; pb.x = tf32r(sc4[nt].z); pb.y = tf32r(sc4[nt].w);
            *(float2*)&Ps[rowB * 68 + c0] = pb;
        }
        __syncwarp();
        // ---- acc += P @ V (tf32 mma) ----
        #pragma unroll
        for (int kc = 0; kc < 64; kc += 8) {
            uint32_t a0 = Psu[rowA * 68 + kc + lc];
            uint32_t a1 = Psu[(rowA + 8) * 68 + kc + lc];
            uint32_t a2 = Psu[rowA * 68 + kc + lc + 4];
            uint32_t a3 = Psu[(rowA + 8) * 68 + kc + lc + 4];
            #pragma unroll
            for (int nt = 0; nt < 8; nt++) {
                uint32_t b0 = Vtu[(nt * 8 + lr) * 68 + kc + lc];
                uint32_t b1 = Vtu[(nt * 8 + lr) * 68 + kc + lc + 4];
                mma8(acc[nt], a0, a1, a2, a3, b0, b1);
            }
        }
    }

    // ---- epilogue: ctx = acc/l + (pw @ emb_v) * exp(mref-m)/l ----
    __syncthreads();
    float* evt = Ks;                       // reuse Ks+Vt: [64(d)][136(rel)]
    uint32_t* evtu = (uint32_t*)evt;
    for (int idx = tid; idx < NREL * HD; idx += 256) {
        const int r = idx >> 6, d = idx & 63;
        evt[d * 136 + r] = tf32r(emb_v[idx]);
    }
    if (tid < 64) {
        #pragma unroll
        for (int r = NREL; r < 136; r++) evt[tid * 136 + r] = 0.f;
    }
    __syncthreads();

    float4 racc[8];
    #pragma unroll
    for (int nt = 0; nt < 8; nt++) racc[nt] = make_float4(0.f, 0.f, 0.f, 0.f);
    #pragma unroll
    for (int kc = 0; kc < 136; kc += 8) {
        uint32_t a0 = __float_as_uint(tf32r(pw[rowA * 136 + kc + lc]));
        uint32_t a1 = __float_as_uint(tf32r(pw[(rowA + 8) * 136 + kc + lc]));
        uint32_t a2 = __float_as_uint(tf32r(pw[rowA * 136 + kc + lc + 4]));
        uint32_t a3 = __float_as_uint(tf32r(pw[(rowA + 8) * 136 + kc + lc + 4]));
        #pragma unroll
        for (int nt = 0; nt < 8; nt++) {
            uint32_t b0 = evtu[(nt * 8 + lr) * 136 + kc + lc];
            uint32_t b1 = evtu[(nt * 8 + lr) * 136 + kc + lc + 4];
            mma8(racc[nt], a0, a1, a2, a3, b0, b1);
        }
    }
    const float rlA = 1.f / l_a, rlB = 1.f / l_b;
    const float eA = __expf(mref_a - m_a) * rlA;
    const float eB = __expf(mref_b - m_b) * rlB;
    #pragma unroll
    for (int nt = 0; nt < 8; nt++) {
        const int c0 = nt * 8 + 2 * lc;
        float2 oa; oa.x = acc[nt].x * rlA + racc[nt].x * eA;
        oa.y = acc[nt].y * rlA + racc[nt].y * eA;
        *(float2*)&Ps[rowA * 68 + c0] = oa;
        float2 ob; ob.x = acc[nt].z * rlB + racc[nt].z * eB;
        ob.y = acc[nt].w * rlB + racc[nt].w * eB;
        *(float2*)&Ps[rowB * 68 + c0] = ob;
    }
    __syncwarp();
    {
        float* op = out + ((size_t)(b * SQ + q0 + r0w)) * DD + h * HD;
        #pragma unroll
        for (int it = 0; it < 8; it++) {
            const int u = lane + 32 * it;
            const int row = u >> 4, c4 = (u & 15) << 2;
            float4 v = *(const float4*)&Ps[(r0w + row) * 68 + c4];
            *(float4*)&op[(size_t)row * DD + c4] = v;
        }
    }
}

// ===========================================================================
extern "C" void kernel_launch(void* const* d_in, const int* in_sizes, int n_in,
                              void* d_out, int out_size)
{
    const float* hidden = (const float*)d_in[0];
    const float* mask   = (const float*)d_in[1];
    const float* Wq     = (const float*)d_in[2];
    const float* bq     = (const float*)d_in[3];
    const float* Wk     = (const float*)d_in[4];
    const float* bk     = (const float*)d_in[5];
    const float* Wv     = (const float*)d_in[6];
    const float* bv     = (const float*)d_in[7];
    const float* emb_k  = (const float*)d_in[8];
    const float* emb_v  = (const float*)d_in[9];
    float* out = (float*)d_out;

    dim3 g1(DD / 128, (BB * SQ) / 128, 3);
    qkv_gemm<<<g1, 256>>>(hidden, Wq, bq, Wk, bk, Wv, bv);

    dim3 g2(SQ / 16, BH);
    qrel_kernel<<<g2, 128>>>(emb_k);

    cudaFuncSetAttribute(attn_tf32, cudaFuncAttributeMaxDynamicSharedMemorySize,
                         ATTN_SMEM_BYTES);
    dim3 g3(SQ / 128, BH);
    attn_tf32<<<g3, 256, ATTN_SMEM_BYTES>>>(mask, emb_v, out);
}

// round 4
// speedup vs baseline: 2.2085x; 1.5250x over previous
#include <cuda_runtime.h>
#include <cuda_bf16.h>
#include <cstdint>

#define BB   2
#define SQ   2048
#define DD   1024
#define NH   16
#define HD   64
#define BH   (BB*NH)      // 32
#define NREL 129
#define QRS  132          // qrel row stride (padded)

// ---------------- scratch (device globals: sanctioned workaround) ----------
__device__ float g_q[(size_t)BH * SQ * HD];      // [bh][s][d]  tf32-rounded
__device__ float g_k[(size_t)BH * SQ * HD];      // [bh][s][d]  tf32-rounded
__device__ float g_vt[(size_t)BH * HD * SQ];     // [bh][d][s]  tf32-rounded, transposed
__device__ float g_qrel[(size_t)BH * SQ * QRS];  // [bh][q][129 (pad 132)]

// ---------------- tf32 helpers --------------------------------------------
__device__ __forceinline__ float tf32r(float x) {
    uint32_t u; asm("cvt.rna.tf32.f32 %0, %1;" : "=r"(u) : "f"(x));
    return __uint_as_float(u);
}
__device__ __forceinline__ void mma8(float4& d,
                                     uint32_t a0, uint32_t a1, uint32_t a2, uint32_t a3,
                                     uint32_t b0, uint32_t b1) {
    asm("mma.sync.aligned.m16n8k8.row.col.f32.tf32.tf32.f32 "
        "{%0,%1,%2,%3},{%4,%5,%6,%7},{%8,%9},{%0,%1,%2,%3};"
        : "+f"(d.x), "+f"(d.y), "+f"(d.z), "+f"(d.w)
        : "r"(a0), "r"(a1), "r"(a2), "r"(a3), "r"(b0), "r"(b1));
}

// ===========================================================================
// Kernel 1: fused QKV projection via tf32 mma, double-buffered smem.
// Stores tf32-rounded outputs; V is stored transposed as [bh][d][s].
// grid: (8, 32, 3), 256 threads.
// ===========================================================================
#define CH 2176   // 16*136 floats per stage buffer

__global__ __launch_bounds__(256) void qkv_gemm(
    const float* __restrict__ X,
    const float* __restrict__ Wq, const float* __restrict__ bq,
    const float* __restrict__ Wk, const float* __restrict__ bk,
    const float* __restrict__ Wv, const float* __restrict__ bv)
{
    __shared__ float As[2 * CH];   // [buf][k][m], stride 136
    __shared__ float Bs[2 * CH];   // [buf][k][n]

    const float* W; const float* bias;
    if (blockIdx.z == 0)      { W = Wq; bias = bq; }
    else if (blockIdx.z == 1) { W = Wk; bias = bk; }
    else                      { W = Wv; bias = bv; }

    const int tid = threadIdx.x;
    const int wid = tid >> 5, lane = tid & 31, lr = lane >> 2, lc = lane & 3;
    const int wm = wid >> 1, wn = wid & 1;
    const int m0 = blockIdx.y * 128, n0 = blockIdx.x * 128;

    const int arow = tid >> 1, acol = (tid & 1) * 8;
    const int brow = tid >> 4, bcol = (tid & 15) * 8;

    float4 acc[2][8];
    #pragma unroll
    for (int mt = 0; mt < 2; mt++)
        #pragma unroll
        for (int nt = 0; nt < 8; nt++) acc[mt][nt] = make_float4(0.f, 0.f, 0.f, 0.f);

    const float* xp = X + (size_t)(m0 + arow) * DD + acol;
    const float* wp = W + (size_t)brow * DD + n0 + bcol;
    float4 xa0 = *(const float4*)(xp);
    float4 xa1 = *(const float4*)(xp + 4);
    float4 wb0 = *(const float4*)(wp);
    float4 wb1 = *(const float4*)(wp + 4);

    uint32_t* Asu = (uint32_t*)As;
    uint32_t* Bsu = (uint32_t*)Bs;

    // stage 0 store
    {
        float* Ab = As; float* Bb = Bs;
        Ab[(acol + 0) * 136 + arow] = tf32r(xa0.x);
        Ab[(acol + 1) * 136 + arow] = tf32r(xa0.y);
        Ab[(acol + 2) * 136 + arow] = tf32r(xa0.z);
        Ab[(acol + 3) * 136 + arow] = tf32r(xa0.w);
        Ab[(acol + 4) * 136 + arow] = tf32r(xa1.x);
        Ab[(acol + 5) * 136 + arow] = tf32r(xa1.y);
        Ab[(acol + 6) * 136 + arow] = tf32r(xa1.z);
        Ab[(acol + 7) * 136 + arow] = tf32r(xa1.w);
        float4 t0 = make_float4(tf32r(wb0.x), tf32r(wb0.y), tf32r(wb0.z), tf32r(wb0.w));
        float4 t1 = make_float4(tf32r(wb1.x), tf32r(wb1.y), tf32r(wb1.z), tf32r(wb1.w));
        *(float4*)&Bb[brow * 136 + bcol]     = t0;
        *(float4*)&Bb[brow * 136 + bcol + 4] = t1;
    }
    __syncthreads();

    for (int k0 = 0; k0 < DD; k0 += 16) {
        const int cur = (k0 >> 4) & 1;
        const bool haveNext = (k0 + 16) < DD;
        if (haveNext) {
            xa0 = *(const float4*)(xp + k0 + 16);
            xa1 = *(const float4*)(xp + k0 + 20);
            wb0 = *(const float4*)(wp + (size_t)(k0 + 16) * DD);
            wb1 = *(const float4*)(wp + (size_t)(k0 + 16) * DD + 4);
        }

        const uint32_t* Ac = Asu + cur * CH;
        const uint32_t* Bc = Bsu + cur * CH;
        #pragma unroll
        for (int kc = 0; kc < 16; kc += 8) {
            uint32_t a[2][4];
            #pragma unroll
            for (int mt = 0; mt < 2; mt++) {
                const int mb = wm * 32 + mt * 16;
                a[mt][0] = Ac[(kc + lc)     * 136 + mb + lr];
                a[mt][1] = Ac[(kc + lc)     * 136 + mb + lr + 8];
                a[mt][2] = Ac[(kc + lc + 4) * 136 + mb + lr];
                a[mt][3] = Ac[(kc + lc + 4) * 136 + mb + lr + 8];
            }
            #pragma unroll
            for (int nt = 0; nt < 8; nt++) {
                const int nb = wn * 64 + nt * 8;
                uint32_t b0 = Bc[(kc + lc)     * 136 + nb + lr];
                uint32_t b1 = Bc[(kc + lc + 4) * 136 + nb + lr];
                mma8(acc[0][nt], a[0][0], a[0][1], a[0][2], a[0][3], b0, b1);
                mma8(acc[1][nt], a[1][0], a[1][1], a[1][2], a[1][3], b0, b1);
            }
        }

        if (haveNext) {
            float* Ab = As + (cur ^ 1) * CH;
            float* Bb = Bs + (cur ^ 1) * CH;
            Ab[(acol + 0) * 136 + arow] = tf32r(xa0.x);
            Ab[(acol + 1) * 136 + arow] = tf32r(xa0.y);
            Ab[(acol + 2) * 136 + arow] = tf32r(xa0.z);
            Ab[(acol + 3) * 136 + arow] = tf32r(xa0.w);
            Ab[(acol + 4) * 136 + arow] = tf32r(xa1.x);
            Ab[(acol + 5) * 136 + arow] = tf32r(xa1.y);
            Ab[(acol + 6) * 136 + arow] = tf32r(xa1.z);
            Ab[(acol + 7) * 136 + arow] = tf32r(xa1.w);
            float4 t0 = make_float4(tf32r(wb0.x), tf32r(wb0.y), tf32r(wb0.z), tf32r(wb0.w));
            float4 t1 = make_float4(tf32r(wb1.x), tf32r(wb1.y), tf32r(wb1.z), tf32r(wb1.w));
            *(float4*)&Bb[brow * 136 + bcol]     = t0;
            *(float4*)&Bb[brow * 136 + bcol + 4] = t1;
        }
        __syncthreads();
    }

    // epilogue: add bias, tf32-round, scatter.
    if (blockIdx.z != 2) {
        float* out = (blockIdx.z == 0) ? g_q : g_k;
        #pragma unroll
        for (int mt = 0; mt < 2; mt++) {
            const int mA = m0 + wm * 32 + mt * 16 + lr;
            const int mB = mA + 8;
            #pragma unroll
            for (int nt = 0; nt < 8; nt++) {
                const int n = n0 + wn * 64 + nt * 8 + 2 * lc;
                const float b0v = __ldg(&bias[n]), b1v = __ldg(&bias[n + 1]);
                const int hh = n >> 6, dd = n & 63;
                {
                    const int bidx = mA >> 11, s = mA & 2047;
                    float2 v; v.x = tf32r(acc[mt][nt].x + b0v); v.y = tf32r(acc[mt][nt].y + b1v);
                    *(float2*)&out[(((size_t)(bidx * NH + hh)) * SQ + s) * HD + dd] = v;
                }
                {
                    const int bidx = mB >> 11, s = mB & 2047;
                    float2 v; v.x = tf32r(acc[mt][nt].z + b0v); v.y = tf32r(acc[mt][nt].w + b1v);
                    *(float2*)&out[(((size_t)(bidx * NH + hh)) * SQ + s) * HD + dd] = v;
                }
            }
        }
    } else {
        // V: transposed scatter into g_vt[bh][d][s]
        #pragma unroll
        for (int mt = 0; mt < 2; mt++) {
            const int mA = m0 + wm * 32 + mt * 16 + lr;
            const int mB = mA + 8;
            const int bA = mA >> 11, sA = mA & 2047;
            const int bB = mB >> 11, sB = mB & 2047;
            #pragma unroll
            for (int nt = 0; nt < 8; nt++) {
                const int n = n0 + wn * 64 + nt * 8 + 2 * lc;
                const float b0v = __ldg(&bias[n]), b1v = __ldg(&bias[n + 1]);
                const int hh = n >> 6, dd = n & 63;
                const size_t base0 = ((size_t)(bA * NH + hh) * HD + dd) * SQ;
                const size_t base1 = ((size_t)(bB * NH + hh) * HD + dd) * SQ;
                g_vt[base0 + sA]       = tf32r(acc[mt][nt].x + b0v);
                g_vt[base0 + SQ + sA]  = tf32r(acc[mt][nt].y + b1v);
                g_vt[base1 + sB]       = tf32r(acc[mt][nt].z + b0v);
                g_vt[base1 + SQ + sB]  = tf32r(acc[mt][nt].w + b1v);
            }
        }
    }
}

// ===========================================================================
// Kernel 2: qrel[bh][q][r] = Q[bh][q][:] . emb_k[r][:]
// grid: (128, 32), 128 threads
// ===========================================================================
__global__ __launch_bounds__(128) void qrel_kernel(const float* __restrict__ emb_k)
{
    __shared__ float ek[NREL * 68];
    const int tid = threadIdx.x;
    const int bh = blockIdx.y, q0 = blockIdx.x * 16;

    for (int idx = tid; idx < NREL * 16; idx += 128) {
        const int r = idx >> 4, d4 = (idx & 15) << 2;
        *(float4*)&ek[r * 68 + d4] = *(const float4*)&emb_k[r * HD + d4];
    }

    const int qi = tid >> 3;
    const int rg = tid & 7;
    float4 qreg[16];
    const float* qp = g_q + (size_t)(bh * SQ + q0 + qi) * HD;
    #pragma unroll
    for (int u = 0; u < 16; u++) qreg[u] = *(const float4*)&qp[u * 4];
    __syncthreads();

    float* orow = g_qrel + (size_t)(bh * SQ + q0 + qi) * QRS;
    for (int r = rg; r < NREL; r += 8) {
        const float* er = ek + r * 68;
        float s = 0.f;
        #pragma unroll
        for (int u = 0; u < 16; u++) {
            float4 e = *(const float4*)&er[u * 4];
            s += qreg[u].x * e.x + qreg[u].y * e.y + qreg[u].z * e.z + qreg[u].w * e.w;
        }
        orow[r] = s;
    }
}

// ===========================================================================
// Kernel 3: flash attention, tf32 mma, far/near relative-position split.
// q-tile 128, k-tile 64, 8 warps; warp owns 16 q rows. Q frags in registers.
// Far tiles (28/32): rel-bias = per-row constant, rel-V hist = row-sum into
// 2 registers. Near tiles (<=4): per-element bias LDG + smem scatter.
// smem: Ks[64*68] Vt[64*68] Ps[128*68] pw[128*136] msk[64] = 139520 B
// ===========================================================================
#define ATTN_SMEM_BYTES (34880 * 4)

__global__ __launch_bounds__(256) void attn_tf32(
    const float* __restrict__ mask,
    const float* __restrict__ emb_v,
    float* __restrict__ out)
{
    extern __shared__ float sm[];
    float* Ks  = sm;              // [64][68]
    float* Vt  = sm + 4352;       // [64(d)][68(s)]
    float* Ps  = sm + 8704;       // [128][68]
    float* pw  = sm + 17408;      // [128][136]
    float* msk = sm + 34816;      // [64]
    uint32_t* Ksu = (uint32_t*)Ks;
    uint32_t* Vtu = (uint32_t*)Vt;
    uint32_t* Psu = (uint32_t*)Ps;

    const int tid = threadIdx.x;
    const int wid = tid >> 5, lane = tid & 31, lr = lane >> 2, lc = lane & 3;
    const int bh = blockIdx.y, b = bh >> 4, h = bh & 15;
    const int q0 = blockIdx.x * 128;
    const int r0w = wid * 16;
    const int rowA = r0w + lr, rowB = rowA + 8;

    for (int i = lane; i < 16 * 136; i += 32) pw[r0w * 136 + i] = 0.f;

    // Q fragments in registers (g_q is tf32-rounded already)
    uint32_t qreg[8][4];
    {
        const float* qpA = g_q + (size_t)(bh * SQ + q0 + rowA) * HD;
        const float* qpB = qpA + (size_t)8 * HD;
        #pragma unroll
        for (int kc = 0; kc < 8; kc++) {
            qreg[kc][0] = __float_as_uint(qpA[kc * 8 + lc]);
            qreg[kc][1] = __float_as_uint(qpB[kc * 8 + lc]);
            qreg[kc][2] = __float_as_uint(qpA[kc * 8 + lc + 4]);
            qreg[kc][3] = __float_as_uint(qpB[kc * 8 + lc + 4]);
        }
    }
    // per-row clamped-bias constants
    const float* qrl = g_qrel + (size_t)bh * SQ * QRS;
    const float* qrA = qrl + (size_t)(q0 + rowA) * QRS;
    const float* qrB = qrl + (size_t)(q0 + rowB) * QRS;
    const float rb0A = qrA[0], rb1A = qrA[128];
    const float rb0B = qrB[0], rb1B = qrB[128];

    float m_a = -1e30f, m_b = -1e30f, l_a = 0.f, l_b = 0.f;
    float mref_a = -1e30f, mref_b = -1e30f;
    float h0A = 0.f, h1A = 0.f, h0B = 0.f, h1B = 0.f;
    float4 acc[8];
    #pragma unroll
    for (int nt = 0; nt < 8; nt++) acc[nt] = make_float4(0.f, 0.f, 0.f, 0.f);

    for (int k0 = 0; k0 < SQ; k0 += 64) {
        __syncthreads();   // previous tile fully consumed
        {
            const int row = tid >> 2, c16 = (tid & 3) * 16;
            const float* kp = g_k  + (size_t)(bh * SQ + k0 + row) * HD + c16;
            const float* vp = g_vt + ((size_t)bh * HD + row) * SQ + k0 + c16;
            #pragma unroll
            for (int u = 0; u < 4; u++) {
                *(float4*)&Ks[row * 68 + c16 + u * 4] = *(const float4*)(kp + u * 4);
                *(float4*)&Vt[row * 68 + c16 + u * 4] = *(const float4*)(vp + u * 4);
            }
        }
        if (tid < 64) msk[tid] = mask[(size_t)b * SQ + k0 + tid];
        __syncthreads();

        const int diff = q0 - k0;
        const bool nearT = (diff >= -128) && (diff <= 64);
        const int delta = diff + 64;

        // ---- scores: S = Q K^T ----
        float4 sc4[8];
        #pragma unroll
        for (int nt = 0; nt < 8; nt++) sc4[nt] = make_float4(0.f, 0.f, 0.f, 0.f);
        #pragma unroll
        for (int kc = 0; kc < 8; kc++) {
            #pragma unroll
            for (int nt = 0; nt < 8; nt++) {
                uint32_t b0 = Ksu[(nt * 8 + lr) * 68 + kc * 8 + lc];
                uint32_t b1 = Ksu[(nt * 8 + lr) * 68 + kc * 8 + lc + 4];
                mma8(sc4[nt], qreg[kc][0], qreg[kc][1], qreg[kc][2], qreg[kc][3], b0, b1);
            }
        }

        // ---- bias + mask + scale ----
        if (nearT) {
            #pragma unroll
            for (int nt = 0; nt < 8; nt++) {
                const int c0 = nt * 8 + 2 * lc;
                const float2 mk = *(const float2*)&msk[c0];
                int bA = rowA + delta - c0;
                int bB = rowB + delta - c0;
                const int bAx = min(max(bA, 0), 128),     bAy = min(max(bA - 1, 0), 128);
                const int bBx = min(max(bB, 0), 128),     bBy = min(max(bB - 1, 0), 128);
                sc4[nt].x = (sc4[nt].x + __ldg(&qrA[bAx])) * 0.125f + mk.x;
                sc4[nt].y = (sc4[nt].y + __ldg(&qrA[bAy])) * 0.125f + mk.y;
                sc4[nt].z = (sc4[nt].z + __ldg(&qrB[bBx])) * 0.125f + mk.x;
                sc4[nt].w = (sc4[nt].w + __ldg(&qrB[bBy])) * 0.125f + mk.y;
            }
        } else {
            const float rbA = (diff > 0) ? rb1A : rb0A;
            const float rbB = (diff > 0) ? rb1B : rb0B;
            #pragma unroll
            for (int nt = 0; nt < 8; nt++) {
                const int c0 = nt * 8 + 2 * lc;
                const float2 mk = *(const float2*)&msk[c0];
                sc4[nt].x = (sc4[nt].x + rbA) * 0.125f + mk.x;
                sc4[nt].y = (sc4[nt].y + rbA) * 0.125f + mk.y;
                sc4[nt].z = (sc4[nt].z + rbB) * 0.125f + mk.x;
                sc4[nt].w = (sc4[nt].w + rbB) * 0.125f + mk.y;
            }
        }

        // ---- online softmax (quad-local) ----
        float mxA = -1e30f, mxB = -1e30f;
        #pragma unroll
        for (int nt = 0; nt < 8; nt++) {
            mxA = fmaxf(mxA, fmaxf(sc4[nt].x, sc4[nt].y));
            mxB = fmaxf(mxB, fmaxf(sc4[nt].z, sc4[nt].w));
        }
        mxA = fmaxf(mxA, __shfl_xor_sync(0xffffffffu, mxA, 1));
        mxA = fmaxf(mxA, __shfl_xor_sync(0xffffffffu, mxA, 2));
        mxB = fmaxf(mxB, __shfl_xor_sync(0xffffffffu, mxB, 1));
        mxB = fmaxf(mxB, __shfl_xor_sync(0xffffffffu, mxB, 2));
        const float nmA = fmaxf(m_a, mxA), nmB = fmaxf(m_b, mxB);
        const float scA = __expf(m_a - nmA), scB = __expf(m_b - nmB);
        float psA = 0.f, psB = 0.f;   // thread-partial row sums
        #pragma unroll
        for (int nt = 0; nt < 8; nt++) {
            sc4[nt].x = __expf(sc4[nt].x - nmA); psA += sc4[nt].x;
            sc4[nt].y = __expf(sc4[nt].y - nmA); psA += sc4[nt].y;
            sc4[nt].z = __expf(sc4[nt].z - nmB); psB += sc4[nt].z;
            sc4[nt].w = __expf(sc4[nt].w - nmB); psB += sc4[nt].w;
        }
        if (mref_a == -1e30f) mref_a = nmA;
        if (mref_b == -1e30f) mref_b = nmB;
        const float fA = __expf(nmA - mref_a);
        const float fB = __expf(nmB - mref_b);

        // ---- rel-V histogram ----
        if (!nearT) {
            if (diff > 0) { h1A += psA * fA; h1B += psB * fB; }
            else          { h0A += psA * fA; h0B += psB * fB; }
        } else {
            #pragma unroll
            for (int nt = 0; nt < 8; nt++) {
                const int c0 = nt * 8 + 2 * lc;
                const int bA = rowA + delta - c0;
                const int bB = rowB + delta - c0;
                const float px = sc4[nt].x * fA, py = sc4[nt].y * fA;
                const float pz = sc4[nt].z * fB, pv = sc4[nt].w * fB;
                if (bA >= 128) h1A += px; else if (bA <= 0) h0A += px; else pw[rowA * 136 + bA] += px;
                if (bA - 1 >= 128) h1A += py; else if (bA - 1 <= 0) h0A += py; else pw[rowA * 136 + bA - 1] += py;
                if (bB >= 128) h1B += pz; else if (bB <= 0) h0B += pz; else pw[rowB * 136 + bB] += pz;
                if (bB - 1 >= 128) h1B += pv; else if (bB - 1 <= 0) h0B += pv; else pw[rowB * 136 + bB - 1] += pv;
            }
        }

        // ---- l/m update, acc rescale ----
        psA += __shfl_xor_sync(0xffffffffu, psA, 1);
        psA += __shfl_xor_sync(0xffffffffu, psA, 2);
        psB += __shfl_xor_sync(0xffffffffu, psB, 1);
        psB += __shfl_xor_sync(0xffffffffu, psB, 2);
        l_a = l_a * scA + psA; m_a = nmA;
        l_b = l_b * scB + psB; m_b = nmB;
        #pragma unroll
        for (int nt = 0; nt < 8; nt++) {
            acc[nt].x *= scA; acc[nt].y *= scA;
            acc[nt].z *= scB; acc[nt].w *= scB;
        }

        // ---- stash P (tf32) ----
        #pragma unroll
        for (int nt = 0; nt < 8; nt++) {
            const int c0 = nt * 8 + 2 * lc;
            float2 pa; pa.x = tf32r(sc4[nt].x); pa.y = tf32r(sc4[nt].y);
            *(float2*)&Ps[rowA * 68 + c0] = pa;
            float2 pb; pb.x = tf32r(sc4[nt].z); pb.y = tf32r(sc4[nt].w);
            *(float2*)&Ps[rowB * 68 + c0] = pb;
        }
        __syncwarp();

        // ---- acc += P @ V ----
        #pragma unroll
        for (int kc = 0; kc < 8; kc++) {
            uint32_t a0 = Psu[rowA * 68 + kc * 8 + lc];
            uint32_t a1 = Psu[(rowA + 8) * 68 + kc * 8 + lc];
            uint32_t a2 = Psu[rowA * 68 + kc * 8 + lc + 4];
            uint32_t a3 = Psu[(rowA + 8) * 68 + kc * 8 + lc + 4];
            #pragma unroll
            for (int nt = 0; nt < 8; nt++) {
                uint32_t b0 = Vtu[(nt * 8 + lr) * 68 + kc * 8 + lc];
                uint32_t b1 = Vtu[(nt * 8 + lr) * 68 + kc * 8 + lc + 4];
                mma8(acc[nt], a0, a1, a2, a3, b0, b1);
            }
        }
    }

    // ---- fold register histogram into pw (rows are warp-private) ----
    h0A += __shfl_xor_sync(0xffffffffu, h0A, 1);
    h0A += __shfl_xor_sync(0xffffffffu, h0A, 2);
    h1A += __shfl_xor_sync(0xffffffffu, h1A, 1);
    h1A += __shfl_xor_sync(0xffffffffu, h1A, 2);
    h0B += __shfl_xor_sync(0xffffffffu, h0B, 1);
    h0B += __shfl_xor_sync(0xffffffffu, h0B, 2);
    h1B += __shfl_xor_sync(0xffffffffu, h1B, 1);
    h1B += __shfl_xor_sync(0xffffffffu, h1B, 2);
    if (lc == 0) {
        pw[rowA * 136 + 0]   += h0A;
        pw[rowA * 136 + 128] += h1A;
        pw[rowB * 136 + 0]   += h0B;
        pw[rowB * 136 + 128] += h1B;
    }
    __syncthreads();

    // ---- epilogue: stage emb_v^T into [d][136], then ctx = acc/l + rel ----
    float* evt = sm;   // reuse Ks+Vt region: 64*136 floats
    uint32_t* evtu = (uint32_t*)evt;
    for (int idx = tid; idx < NREL * HD; idx += 256) {
        const int r = idx >> 6, d = idx & 63;
        evt[d * 136 + r] = tf32r(emb_v[idx]);
    }
    if (tid < 64) {
        #pragma unroll
        for (int r = NREL; r < 136; r++) evt[tid * 136 + r] = 0.f;
    }
    __syncthreads();

    float4 racc[8];
    #pragma unroll
    for (int nt = 0; nt < 8; nt++) racc[nt] = make_float4(0.f, 0.f, 0.f, 0.f);
    #pragma unroll
    for (int kc = 0; kc < 136; kc += 8) {
        uint32_t a0 = __float_as_uint(tf32r(pw[rowA * 136 + kc + lc]));
        uint32_t a1 = __float_as_uint(tf32r(pw[(rowA + 8) * 136 + kc + lc]));
        uint32_t a2 = __float_as_uint(tf32r(pw[rowA * 136 + kc + lc + 4]));
        uint32_t a3 = __float_as_uint(tf32r(pw[(rowA + 8) * 136 + kc + lc + 4]));
        #pragma unroll
        for (int nt = 0; nt < 8; nt++) {
            uint32_t b0 = evtu[(nt * 8 + lr) * 136 + kc + lc];
            uint32_t b1 = evtu[(nt * 8 + lr) * 136 + kc + lc + 4];
            mma8(racc[nt], a0, a1, a2, a3, b0, b1);
        }
    }
    const float rlA = 1.f / l_a, rlB = 1.f / l_b;
    const float eA = __expf(mref_a - m_a) * rlA;
    const float eB = __expf(mref_b - m_b) * rlB;
    #pragma unroll
    for (int nt = 0; nt < 8; nt++) {
        const int c0 = nt * 8 + 2 * lc;
        float2 oa; oa.x = acc[nt].x * rlA + racc[nt].x * eA;
        oa.y = acc[nt].y * rlA + racc[nt].y * eA;
        *(float2*)&Ps[rowA * 68 + c0] = oa;
        float2 ob; ob.x = acc[nt].z * rlB + racc[nt].z * eB;
        ob.y = acc[nt].w * rlB + racc[nt].w * eB;
        *(float2*)&Ps[rowB * 68 + c0] = ob;
    }
    __syncwarp();
    {
        float* op = out + ((size_t)(b * SQ + q0 + r0w)) * DD + h * HD;
        #pragma unroll
        for (int it = 0; it < 8; it++) {
            const int u = lane + 32 * it;
            const int row = u >> 4, c4 = (u & 15) << 2;
            float4 v = *(const float4*)&Ps[(r0w + row) * 68 + c4];
            *(float4*)&op[(size_t)row * DD + c4] = v;
        }
    }
}

// ===========================================================================
extern "C" void kernel_launch(void* const* d_in, const int* in_sizes, int n_in,
                              void* d_out, int out_size)
{
    const float* hidden = (const float*)d_in[0];
    const float* mask   = (const float*)d_in[1];
    const float* Wq     = (const float*)d_in[2];
    const float* bq     = (const float*)d_in[3];
    const float* Wk     = (const float*)d_in[4];
    const float* bk     = (const float*)d_in[5];
    const float* Wv     = (const float*)d_in[6];
    const float* bv     = (const float*)d_in[7];
    const float* emb_k  = (const float*)d_in[8];
    const float* emb_v  = (const float*)d_in[9];
    float* out = (float*)d_out;

    dim3 g1(DD / 128, (BB * SQ) / 128, 3);
    qkv_gemm<<<g1, 256>>>(hidden, Wq, bq, Wk, bk, Wv, bv);

    dim3 g2(SQ / 16, BH);
    qrel_kernel<<<g2, 128>>>(emb_k);

    cudaFuncSetAttribute(attn_tf32, cudaFuncAttributeMaxDynamicSharedMemorySize,
                         ATTN_SMEM_BYTES);
    dim3 g3(SQ / 128, BH);
    attn_tf32<<<g3, 256, ATTN_SMEM_BYTES>>>(mask, emb_v, out);
}

// round 5
// speedup vs baseline: 2.2167x; 1.0037x over previous
#include <cuda_runtime.h>
#include <cuda_bf16.h>
#include <cstdint>

#define BB   2
#define SQ   2048
#define DD   1024
#define NH   16
#define HD   64
#define BH   (BB*NH)      // 32
#define NREL 129
#define QRS  132          // qrel row stride (padded)

// ---------------- scratch (device globals: sanctioned workaround) ----------
__device__ float g_q[(size_t)BH * SQ * HD];      // [bh][s][d]  tf32-rounded
__device__ float g_k[(size_t)BH * SQ * HD];      // [bh][s][d]  tf32-rounded
__device__ float g_vt[(size_t)BH * HD * SQ];     // [bh][d][s]  tf32-rounded, transposed
__device__ float g_qrel[(size_t)BH * SQ * QRS];  // [bh][q][129 (pad 132)]

// ---------------- tf32 helpers --------------------------------------------
__device__ __forceinline__ float tf32r(float x) {
    uint32_t u; asm("cvt.rna.tf32.f32 %0, %1;" : "=r"(u) : "f"(x));
    return __uint_as_float(u);
}
__device__ __forceinline__ void mma8(float4& d,
                                     uint32_t a0, uint32_t a1, uint32_t a2, uint32_t a3,
                                     uint32_t b0, uint32_t b1) {
    asm("mma.sync.aligned.m16n8k8.row.col.f32.tf32.tf32.f32 "
        "{%0,%1,%2,%3},{%4,%5,%6,%7},{%8,%9},{%0,%1,%2,%3};"
        : "+f"(d.x), "+f"(d.y), "+f"(d.z), "+f"(d.w)
        : "r"(a0), "r"(a1), "r"(a2), "r"(a3), "r"(b0), "r"(b1));
}

// ===========================================================================
// Kernel 1: fused QKV projection via tf32 mma, double-buffered smem.
// Stores tf32-rounded outputs; V is stored transposed as [bh][d][s].
// grid: (8, 32, 3), 256 threads.
// ===========================================================================
#define CH 2176   // 16*136 floats per stage buffer

__global__ __launch_bounds__(256) void qkv_gemm(
    const float* __restrict__ X,
    const float* __restrict__ Wq, const float* __restrict__ bq,
    const float* __restrict__ Wk, const float* __restrict__ bk,
    const float* __restrict__ Wv, const float* __restrict__ bv)
{
    __shared__ float As[2 * CH];   // [buf][k][m], stride 136
    __shared__ float Bs[2 * CH];   // [buf][k][n]

    const float* W; const float* bias;
    if (blockIdx.z == 0)      { W = Wq; bias = bq; }
    else if (blockIdx.z == 1) { W = Wk; bias = bk; }
    else                      { W = Wv; bias = bv; }

    const int tid = threadIdx.x;
    const int wid = tid >> 5, lane = tid & 31, lr = lane >> 2, lc = lane & 3;
    const int wm = wid >> 1, wn = wid & 1;
    const int m0 = blockIdx.y * 128, n0 = blockIdx.x * 128;

    const int arow = tid >> 1, acol = (tid & 1) * 8;
    const int brow = tid >> 4, bcol = (tid & 15) * 8;

    float4 acc[2][8];
    #pragma unroll
    for (int mt = 0; mt < 2; mt++)
        #pragma unroll
        for (int nt = 0; nt < 8; nt++) acc[mt][nt] = make_float4(0.f, 0.f, 0.f, 0.f);

    const float* xp = X + (size_t)(m0 + arow) * DD + acol;
    const float* wp = W + (size_t)brow * DD + n0 + bcol;
    float4 xa0 = *(const float4*)(xp);
    float4 xa1 = *(const float4*)(xp + 4);
    float4 wb0 = *(const float4*)(wp);
    float4 wb1 = *(const float4*)(wp + 4);

    uint32_t* Asu = (uint32_t*)As;
    uint32_t* Bsu = (uint32_t*)Bs;

    // stage 0 store
    {
        float* Ab = As; float* Bb = Bs;
        Ab[(acol + 0) * 136 + arow] = tf32r(xa0.x);
        Ab[(acol + 1) * 136 + arow] = tf32r(xa0.y);
        Ab[(acol + 2) * 136 + arow] = tf32r(xa0.z);
        Ab[(acol + 3) * 136 + arow] = tf32r(xa0.w);
        Ab[(acol + 4) * 136 + arow] = tf32r(xa1.x);
        Ab[(acol + 5) * 136 + arow] = tf32r(xa1.y);
        Ab[(acol + 6) * 136 + arow] = tf32r(xa1.z);
        Ab[(acol + 7) * 136 + arow] = tf32r(xa1.w);
        float4 t0 = make_float4(tf32r(wb0.x), tf32r(wb0.y), tf32r(wb0.z), tf32r(wb0.w));
        float4 t1 = make_float4(tf32r(wb1.x), tf32r(wb1.y), tf32r(wb1.z), tf32r(wb1.w));
        *(float4*)&Bb[brow * 136 + bcol]     = t0;
        *(float4*)&Bb[brow * 136 + bcol + 4] = t1;
    }
    __syncthreads();

    for (int k0 = 0; k0 < DD; k0 += 16) {
        const int cur = (k0 >> 4) & 1;
        const bool haveNext = (k0 + 16) < DD;
        if (haveNext) {
            xa0 = *(const float4*)(xp + k0 + 16);
            xa1 = *(const float4*)(xp + k0 + 20);
            wb0 = *(const float4*)(wp + (size_t)(k0 + 16) * DD);
            wb1 = *(const float4*)(wp + (size_t)(k0 + 16) * DD + 4);
        }

        const uint32_t* Ac = Asu + cur * CH;
        const uint32_t* Bc = Bsu + cur * CH;
        #pragma unroll
        for (int kc = 0; kc < 16; kc += 8) {
            uint32_t a[2][4];
            #pragma unroll
            for (int mt = 0; mt < 2; mt++) {
                const int mb = wm * 32 + mt * 16;
                a[mt][0] = Ac[(kc + lc)     * 136 + mb + lr];
                a[mt][1] = Ac[(kc + lc)     * 136 + mb + lr + 8];
                a[mt][2] = Ac[(kc + lc + 4) * 136 + mb + lr];
                a[mt][3] = Ac[(kc + lc + 4) * 136 + mb + lr + 8];
            }
            #pragma unroll
            for (int nt = 0; nt < 8; nt++) {
                const int nb = wn * 64 + nt * 8;
                uint32_t b0 = Bc[(kc + lc)     * 136 + nb + lr];
                uint32_t b1 = Bc[(kc + lc + 4) * 136 + nb + lr];
                mma8(acc[0][nt], a[0][0], a[0][1], a[0][2], a[0][3], b0, b1);
                mma8(acc[1][nt], a[1][0], a[1][1], a[1][2], a[1][3], b0, b1);
            }
        }

        if (haveNext) {
            float* Ab = As + (cur ^ 1) * CH;
            float* Bb = Bs + (cur ^ 1) * CH;
            Ab[(acol + 0) * 136 + arow] = tf32r(xa0.x);
            Ab[(acol + 1) * 136 + arow] = tf32r(xa0.y);
            Ab[(acol + 2) * 136 + arow] = tf32r(xa0.z);
            Ab[(acol + 3) * 136 + arow] = tf32r(xa0.w);
            Ab[(acol + 4) * 136 + arow] = tf32r(xa1.x);
            Ab[(acol + 5) * 136 + arow] = tf32r(xa1.y);
            Ab[(acol + 6) * 136 + arow] = tf32r(xa1.z);
            Ab[(acol + 7) * 136 + arow] = tf32r(xa1.w);
            float4 t0 = make_float4(tf32r(wb0.x), tf32r(wb0.y), tf32r(wb0.z), tf32r(wb0.w));
            float4 t1 = make_float4(tf32r(wb1.x), tf32r(wb1.y), tf32r(wb1.z), tf32r(wb1.w));
            *(float4*)&Bb[brow * 136 + bcol]     = t0;
            *(float4*)&Bb[brow * 136 + bcol + 4] = t1;
        }
        __syncthreads();
    }

    // epilogue: add bias, tf32-round, scatter.
    if (blockIdx.z != 2) {
        float* out = (blockIdx.z == 0) ? g_q : g_k;
        #pragma unroll
        for (int mt = 0; mt < 2; mt++) {
            const int mA = m0 + wm * 32 + mt * 16 + lr;
            const int mB = mA + 8;
            #pragma unroll
            for (int nt = 0; nt < 8; nt++) {
                const int n = n0 + wn * 64 + nt * 8 + 2 * lc;
                const float b0v = __ldg(&bias[n]), b1v = __ldg(&bias[n + 1]);
                const int hh = n >> 6, dd = n & 63;
                {
                    const int bidx = mA >> 11, s = mA & 2047;
                    float2 v; v.x = tf32r(acc[mt][nt].x + b0v); v.y = tf32r(acc[mt][nt].y + b1v);
                    *(float2*)&out[(((size_t)(bidx * NH + hh)) * SQ + s) * HD + dd] = v;
                }
                {
                    const int bidx = mB >> 11, s = mB & 2047;
                    float2 v; v.x = tf32r(acc[mt][nt].z + b0v); v.y = tf32r(acc[mt][nt].w + b1v);
                    *(float2*)&out[(((size_t)(bidx * NH + hh)) * SQ + s) * HD + dd] = v;
                }
            }
        }
    } else {
        // V: transposed scatter into g_vt[bh][d][s]
        #pragma unroll
        for (int mt = 0; mt < 2; mt++) {
            const int mA = m0 + wm * 32 + mt * 16 + lr;
            const int mB = mA + 8;
            const int bA = mA >> 11, sA = mA & 2047;
            const int bB = mB >> 11, sB = mB & 2047;
            #pragma unroll
            for (int nt = 0; nt < 8; nt++) {
                const int n = n0 + wn * 64 + nt * 8 + 2 * lc;
                const float b0v = __ldg(&bias[n]), b1v = __ldg(&bias[n + 1]);
                const int hh = n >> 6, dd = n & 63;
                const size_t base0 = ((size_t)(bA * NH + hh) * HD + dd) * SQ;
                const size_t base1 = ((size_t)(bB * NH + hh) * HD + dd) * SQ;
                g_vt[base0 + sA]       = tf32r(acc[mt][nt].x + b0v);
                g_vt[base0 + SQ + sA]  = tf32r(acc[mt][nt].y + b1v);
                g_vt[base1 + sB]       = tf32r(acc[mt][nt].z + b0v);
                g_vt[base1 + SQ + sB]  = tf32r(acc[mt][nt].w + b1v);
            }
        }
    }
}

// ===========================================================================
// Kernel 2: qrel[bh][q][r] = Q[bh][q][:] . emb_k[r][:]
// grid: (128, 32), 128 threads
// ===========================================================================
__global__ __launch_bounds__(128) void qrel_kernel(const float* __restrict__ emb_k)
{
    __shared__ float ek[NREL * 68];
    const int tid = threadIdx.x;
    const int bh = blockIdx.y, q0 = blockIdx.x * 16;

    for (int idx = tid; idx < NREL * 16; idx += 128) {
        const int r = idx >> 4, d4 = (idx & 15) << 2;
        *(float4*)&ek[r * 68 + d4] = *(const float4*)&emb_k[r * HD + d4];
    }

    const int qi = tid >> 3;
    const int rg = tid & 7;
    float4 qreg[16];
    const float* qp = g_q + (size_t)(bh * SQ + q0 + qi) * HD;
    #pragma unroll
    for (int u = 0; u < 16; u++) qreg[u] = *(const float4*)&qp[u * 4];
    __syncthreads();

    float* orow = g_qrel + (size_t)(bh * SQ + q0 + qi) * QRS;
    for (int r = rg; r < NREL; r += 8) {
        const float* er = ek + r * 68;
        float s = 0.f;
        #pragma unroll
        for (int u = 0; u < 16; u++) {
            float4 e = *(const float4*)&er[u * 4];
            s += qreg[u].x * e.x + qreg[u].y * e.y + qreg[u].z * e.z + qreg[u].w * e.w;
        }
        orow[r] = s;
    }
}

// ===========================================================================
// Kernel 3: flash attention, tf32 mma, far/near relative-position split.
// q-tile 128, k-tile 64, 8 warps; warp owns 16 q rows. Q frags in registers.
// Far tiles (28/32): rel-bias = per-row constant, rel-V hist = row-sum into
// 2 registers. Near tiles (<=4): per-element bias LDG + smem scatter.
// smem: Ks[64*68] Vt[64*68] Ps[128*68] pw[128*136] msk[64] = 139520 B
// ===========================================================================
#define ATTN_SMEM_BYTES (34880 * 4)

__global__ __launch_bounds__(256) void attn_tf32(
    const float* __restrict__ mask,
    const float* __restrict__ emb_v,
    float* __restrict__ out)
{
    extern __shared__ float sm[];
    float* Ks  = sm;              // [64][68]
    float* Vt  = sm + 4352;       // [64(d)][68(s)]
    float* Ps  = sm + 8704;       // [128][68]
    float* pw  = sm + 17408;      // [128][136]
    float* msk = sm + 34816;      // [64]
    uint32_t* Ksu = (uint32_t*)Ks;
    uint32_t* Vtu = (uint32_t*)Vt;
    uint32_t* Psu = (uint32_t*)Ps;

    const int tid = threadIdx.x;
    const int wid = tid >> 5, lane = tid & 31, lr = lane >> 2, lc = lane & 3;
    const int bh = blockIdx.y, b = bh >> 4, h = bh & 15;
    const int q0 = blockIdx.x * 128;
    const int r0w = wid * 16;
    const int rowA = r0w + lr, rowB = rowA + 8;

    for (int i = lane; i < 16 * 136; i += 32) pw[r0w * 136 + i] = 0.f;

    // Q fragments in registers (g_q is tf32-rounded already)
    uint32_t qreg[8][4];
    {
        const float* qpA = g_q + (size_t)(bh * SQ + q0 + rowA) * HD;
        const float* qpB = qpA + (size_t)8 * HD;
        #pragma unroll
        for (int kc = 0; kc < 8; kc++) {
            qreg[kc][0] = __float_as_uint(qpA[kc * 8 + lc]);
            qreg[kc][1] = __float_as_uint(qpB[kc * 8 + lc]);
            qreg[kc][2] = __float_as_uint(qpA[kc * 8 + lc + 4]);
            qreg[kc][3] = __float_as_uint(qpB[kc * 8 + lc + 4]);
        }
    }
    // per-row clamped-bias constants
    const float* qrl = g_qrel + (size_t)bh * SQ * QRS;
    const float* qrA = qrl + (size_t)(q0 + rowA) * QRS;
    const float* qrB = qrl + (size_t)(q0 + rowB) * QRS;
    const float rb0A = qrA[0], rb1A = qrA[128];
    const float rb0B = qrB[0], rb1B = qrB[128];

    float m_a = -1e30f, m_b = -1e30f, l_a = 0.f, l_b = 0.f;
    float mref_a = -1e30f, mref_b = -1e30f;
    float h0A = 0.f, h1A = 0.f, h0B = 0.f, h1B = 0.f;
    float4 acc[8];
    #pragma unroll
    for (int nt = 0; nt < 8; nt++) acc[nt] = make_float4(0.f, 0.f, 0.f, 0.f);

    for (int k0 = 0; k0 < SQ; k0 += 64) {
        __syncthreads();   // previous tile fully consumed
        {
            const int row = tid >> 2, c16 = (tid & 3) * 16;
            const float* kp = g_k  + (size_t)(bh * SQ + k0 + row) * HD + c16;
            const float* vp = g_vt + ((size_t)bh * HD + row) * SQ + k0 + c16;
            #pragma unroll
            for (int u = 0; u < 4; u++) {
                *(float4*)&Ks[row * 68 + c16 + u * 4] = *(const float4*)(kp + u * 4);
                *(float4*)&Vt[row * 68 + c16 + u * 4] = *(const float4*)(vp + u * 4);
            }
        }
        if (tid < 64) msk[tid] = mask[(size_t)b * SQ + k0 + tid];
        __syncthreads();

        const int diff = q0 - k0;
        const bool nearT = (diff >= -128) && (diff <= 64);
        const int delta = diff + 64;

        // ---- scores: S = Q K^T ----
        float4 sc4[8];
        #pragma unroll
        for (int nt = 0; nt < 8; nt++) sc4[nt] = make_float4(0.f, 0.f, 0.f, 0.f);
        #pragma unroll
        for (int kc = 0; kc < 8; kc++) {
            #pragma unroll
            for (int nt = 0; nt < 8; nt++) {
                uint32_t b0 = Ksu[(nt * 8 + lr) * 68 + kc * 8 + lc];
                uint32_t b1 = Ksu[(nt * 8 + lr) * 68 + kc * 8 + lc + 4];
                mma8(sc4[nt], qreg[kc][0], qreg[kc][1], qreg[kc][2], qreg[kc][3], b0, b1);
            }
        }

        // ---- bias + mask + scale ----
        if (nearT) {
            #pragma unroll
            for (int nt = 0; nt < 8; nt++) {
                const int c0 = nt * 8 + 2 * lc;
                const float2 mk = *(const float2*)&msk[c0];
                int bA = rowA + delta - c0;
                int bB = rowB + delta - c0;
                const int bAx = min(max(bA, 0), 128),     bAy = min(max(bA - 1, 0), 128);
                const int bBx = min(max(bB, 0), 128),     bBy = min(max(bB - 1, 0), 128);
                sc4[nt].x = (sc4[nt].x + __ldg(&qrA[bAx])) * 0.125f + mk.x;
                sc4[nt].y = (sc4[nt].y + __ldg(&qrA[bAy])) * 0.125f + mk.y;
                sc4[nt].z = (sc4[nt].z + __ldg(&qrB[bBx])) * 0.125f + mk.x;
                sc4[nt].w = (sc4[nt].w + __ldg(&qrB[bBy])) * 0.125f + mk.y;
            }
        } else {
            const float rbA = (diff > 0) ? rb1A : rb0A;
            const float rbB = (diff > 0) ? rb1B : rb0B;
            #pragma unroll
            for (int nt = 0; nt < 8; nt++) {
                const int c0 = nt * 8 + 2 * lc;
                const float2 mk = *(const float2*)&msk[c0];
                sc4[nt].x = (sc4[nt].x + rbA) * 0.125f + mk.x;
                sc4[nt].y = (sc4[nt].y + rbA) * 0.125f + mk.y;
                sc4[nt].z = (sc4[nt].z + rbB) * 0.125f + mk.x;
                sc4[nt].w = (sc4[nt].w + rbB) * 0.125f + mk.y;
            }
        }

        // ---- online softmax (quad-local) ----
        float mxA = -1e30f, mxB = -1e30f;
        #pragma unroll
        for (int nt = 0; nt < 8; nt++) {
            mxA = fmaxf(mxA, fmaxf(sc4[nt].x, sc4[nt].y));
            mxB = fmaxf(mxB, fmaxf(sc4[nt].z, sc4[nt].w));
        }
        mxA = fmaxf(mxA, __shfl_xor_sync(0xffffffffu, mxA, 1));
        mxA = fmaxf(mxA, __shfl_xor_sync(0xffffffffu, mxA, 2));
        mxB = fmaxf(mxB, __shfl_xor_sync(0xffffffffu, mxB, 1));
        mxB = fmaxf(mxB, __shfl_xor_sync(0xffffffffu, mxB, 2));
        const float nmA = fmaxf(m_a, mxA), nmB = fmaxf(m_b, mxB);
        const float scA = __expf(m_a - nmA), scB = __expf(m_b - nmB);
        float psA = 0.f, psB = 0.f;   // thread-partial row sums
        #pragma unroll
        for (int nt = 0; nt < 8; nt++) {
            sc4[nt].x = __expf(sc4[nt].x - nmA); psA += sc4[nt].x;
            sc4[nt].y = __expf(sc4[nt].y - nmA); psA += sc4[nt].y;
            sc4[nt].z = __expf(sc4[nt].z - nmB); psB += sc4[nt].z;
            sc4[nt].w = __expf(sc4[nt].w - nmB); psB += sc4[nt].w;
        }
        if (mref_a == -1e30f) mref_a = nmA;
        if (mref_b == -1e30f) mref_b = nmB;
        const float fA = __expf(nmA - mref_a);
        const float fB = __expf(nmB - mref_b);

        // ---- rel-V histogram ----
        if (!nearT) {
            if (diff > 0) { h1A += psA * fA; h1B += psB * fB; }
            else          { h0A += psA * fA; h0B += psB * fB; }
        } else {
            #pragma unroll
            for (int nt = 0; nt < 8; nt++) {
                const int c0 = nt * 8 + 2 * lc;
                const int bA = rowA + delta - c0;
                const int bB = rowB + delta - c0;
                const float px = sc4[nt].x * fA, py = sc4[nt].y * fA;
                const float pz = sc4[nt].z * fB, pv = sc4[nt].w * fB;
                if (bA >= 128) h1A += px; else if (bA <= 0) h0A += px; else pw[rowA * 136 + bA] += px;
                if (bA - 1 >= 128) h1A += py; else if (bA - 1 <= 0) h0A += py; else pw[rowA * 136 + bA - 1] += py;
                if (bB >= 128) h1B += pz; else if (bB <= 0) h0B += pz; else pw[rowB * 136 + bB] += pz;
                if (bB - 1 >= 128) h1B += pv; else if (bB - 1 <= 0) h0B += pv; else pw[rowB * 136 + bB - 1] += pv;
            }
        }

        // ---- l/m update, acc rescale ----
        psA += __shfl_xor_sync(0xffffffffu, psA, 1);
        psA += __shfl_xor_sync(0xffffffffu, psA, 2);
        psB += __shfl_xor_sync(0xffffffffu, psB, 1);
        psB += __shfl_xor_sync(0xffffffffu, psB, 2);
        l_a = l_a * scA + psA; m_a = nmA;
        l_b = l_b * scB + psB; m_b = nmB;
        #pragma unroll
        for (int nt = 0; nt < 8; nt++) {
            acc[nt].x *= scA; acc[nt].y *= scA;
            acc[nt].z *= scB; acc[nt].w *= scB;
        }

        // ---- stash P (tf32) ----
        #pragma unroll
        for (int nt = 0; nt < 8; nt++) {
            const int c0 = nt * 8 + 2 * lc;
            float2 pa; pa.x = tf32r(sc4[nt].x); pa.y = tf32r(sc4[nt].y);
            *(float2*)&Ps[rowA * 68 + c0] = pa;
            float2 pb; pb.x = tf32r(sc4[nt].z); pb.y = tf32r(sc4[nt].w);
            *(float2*)&Ps[rowB * 68 + c0] = pb;
        }
        __syncwarp();

        // ---- acc += P @ V ----
        #pragma unroll
        for (int kc = 0; kc < 8; kc++) {
            uint32_t a0 = Psu[rowA * 68 + kc * 8 + lc];
            uint32_t a1 = Psu[(rowA + 8) * 68 + kc * 8 + lc];
            uint32_t a2 = Psu[rowA * 68 + kc * 8 + lc + 4];
            uint32_t a3 = Psu[(rowA + 8) * 68 + kc * 8 + lc + 4];
            #pragma unroll
            for (int nt = 0; nt < 8; nt++) {
                uint32_t b0 = Vtu[(nt * 8 + lr) * 68 + kc * 8 + lc];
                uint32_t b1 = Vtu[(nt * 8 + lr) * 68 + kc * 8 + lc + 4];
                mma8(acc[nt], a0, a1, a2, a3, b0, b1);
            }
        }
    }

    // ---- fold register histogram into pw (rows are warp-private) ----
    h0A += __shfl_xor_sync(0xffffffffu, h0A, 1);
    h0A += __shfl_xor_sync(0xffffffffu, h0A, 2);
    h1A += __shfl_xor_sync(0xffffffffu, h1A, 1);
    h1A += __shfl_xor_sync(0xffffffffu, h1A, 2);
    h0B += __shfl_xor_sync(0xffffffffu, h0B, 1);
    h0B += __shfl_xor_sync(0xffffffffu, h0B, 2);
    h1B += __shfl_xor_sync(0xffffffffu, h1B, 1);
    h1B += __shfl_xor_sync(0xffffffffu, h1B, 2);
    if (lc == 0) {
        pw[rowA * 136 + 0]   += h0A;
        pw[rowA * 136 + 128] += h1A;
        pw[rowB * 136 + 0]   += h0B;
        pw[rowB * 136 + 128] += h1B;
    }
    __syncthreads();

    // ---- epilogue: stage emb_v^T into [d][136], then ctx = acc/l + rel ----
    float* evt = sm;   // reuse Ks+Vt region: 64*136 floats
    uint32_t* evtu = (uint32_t*)evt;
    for (int idx = tid; idx < NREL * HD; idx += 256) {
        const int r = idx >> 6, d = idx & 63;
        evt[d * 136 + r] = tf32r(emb_v[idx]);
    }
    if (tid < 64) {
        #pragma unroll
        for (int r = NREL; r < 136; r++) evt[tid * 136 + r] = 0.f;
    }
    __syncthreads();

    float4 racc[8];
    #pragma unroll
    for (int nt = 0; nt < 8; nt++) racc[nt] = make_float4(0.f, 0.f, 0.f, 0.f);
    #pragma unroll
    for (int kc = 0; kc < 136; kc += 8) {
        uint32_t a0 = __float_as_uint(tf32r(pw[rowA * 136 + kc + lc]));
        uint32_t a1 = __float_as_uint(tf32r(pw[(rowA + 8) * 136 + kc + lc]));
        uint32_t a2 = __float_as_uint(tf32r(pw[rowA * 136 + kc + lc + 4]));
        uint32_t a3 = __float_as_uint(tf32r(pw[(rowA + 8) * 136 + kc + lc + 4]));
        #pragma unroll
        for (int nt = 0; nt < 8; nt++) {
            uint32_t b0 = evtu[(nt * 8 + lr) * 136 + kc + lc];
            uint32_t b1 = evtu[(nt * 8 + lr) * 136 + kc + lc + 4];
            mma8(racc[nt], a0, a1, a2, a3, b0, b1);
        }
    }
    const float rlA = 1.f / l_a, rlB = 1.f / l_b;
    const float eA = __expf(mref_a - m_a) * rlA;
    const float eB = __expf(mref_b - m_b) * rlB;
    #pragma unroll
    for (int nt = 0; nt < 8; nt++) {
        const int c0 = nt * 8 + 2 * lc;
        float2 oa; oa.x = acc[nt].x * rlA + racc[nt].x * eA;
        oa.y = acc[nt].y * rlA + racc[nt].y * eA;
        *(float2*)&Ps[rowA * 68 + c0] = oa;
        float2 ob; ob.x = acc[nt].z * rlB + racc[nt].z * eB;
        ob.y = acc[nt].w * rlB + racc[nt].w * eB;
        *(float2*)&Ps[rowB * 68 + c0] = ob;
    }
    __syncwarp();
    {
        float* op = out + ((size_t)(b * SQ + q0 + r0w)) * DD + h * HD;
        #pragma unroll
        for (int it = 0; it < 8; it++) {
            const int u = lane + 32 * it;
            const int row = u >> 4, c4 = (u & 15) << 2;
            float4 v = *(const float4*)&Ps[(r0w + row) * 68 + c4];
            *(float4*)&op[(size_t)row * DD + c4] = v;
        }
    }
}

// ===========================================================================
extern "C" void kernel_launch(void* const* d_in, const int* in_sizes, int n_in,
                              void* d_out, int out_size)
{
    const float* hidden = (const float*)d_in[0];
    const float* mask   = (const float*)d_in[1];
    const float* Wq     = (const float*)d_in[2];
    const float* bq     = (const float*)d_in[3];
    const float* Wk     = (const float*)d_in[4];
    const float* bk     = (const float*)d_in[5];
    const float* Wv     = (const float*)d_in[6];
    const float* bv     = (const float*)d_in[7];
    const float* emb_k  = (const float*)d_in[8];
    const float* emb_v  = (const float*)d_in[9];
    float* out = (float*)d_out;

    dim3 g1(DD / 128, (BB * SQ) / 128, 3);
    qkv_gemm<<<g1, 256>>>(hidden, Wq, bq, Wk, bk, Wv, bv);

    dim3 g2(SQ / 16, BH);
    qrel_kernel<<<g2, 128>>>(emb_k);

    cudaFuncSetAttribute(attn_tf32, cudaFuncAttributeMaxDynamicSharedMemorySize,
                         ATTN_SMEM_BYTES);
    dim3 g3(SQ / 128, BH);
    attn_tf32<<<g3, 256, ATTN_SMEM_BYTES>>>(mask, emb_v, out);
}

// round 7
// speedup vs baseline: 2.2813x; 1.0292x over previous
#include <cuda_runtime.h>
#include <cuda_bf16.h>
#include <cstdint>

#define BB   2
#define SQ   2048
#define DD   1024
#define NH   16
#define HD   64
#define BH   (BB*NH)      // 32
#define NREL 129
#define QRS  132          // qrel row stride (padded)

// ---------------- scratch (device globals: sanctioned workaround) ----------
__device__ float g_q[(size_t)BH * SQ * HD];      // [bh][s][d]  tf32-rounded
__device__ float g_k[(size_t)BH * SQ * HD];      // [bh][s][d]  tf32-rounded
__device__ float g_vt[(size_t)BH * HD * SQ];     // [bh][d][s]  tf32-rounded, transposed
__device__ float g_qrel[(size_t)BH * SQ * QRS];  // [bh][q][129 (pad 132)]

// ---------------- tf32 helpers --------------------------------------------
__device__ __forceinline__ float tf32r(float x) {
    uint32_t u; asm("cvt.rna.tf32.f32 %0, %1;" : "=r"(u) : "f"(x));
    return __uint_as_float(u);
}
__device__ __forceinline__ uint32_t tf32b(float x) {
    uint32_t u; asm("cvt.rna.tf32.f32 %0, %1;" : "=r"(u) : "f"(x));
    return u;
}
__device__ __forceinline__ float ex2f(float x) {
    float r; asm("ex2.approx.f32 %0, %1;" : "=f"(r) : "f"(x));
    return r;
}
__device__ __forceinline__ void mma8(float4& d,
                                     uint32_t a0, uint32_t a1, uint32_t a2, uint32_t a3,
                                     uint32_t b0, uint32_t b1) {
    asm("mma.sync.aligned.m16n8k8.row.col.f32.tf32.tf32.f32 "
        "{%0,%1,%2,%3},{%4,%5,%6,%7},{%8,%9},{%0,%1,%2,%3};"
        : "+f"(d.x), "+f"(d.y), "+f"(d.z), "+f"(d.w)
        : "r"(a0), "r"(a1), "r"(a2), "r"(a3), "r"(b0), "r"(b1));
}

// ===========================================================================
// Kernel 1: fused QKV projection via tf32 mma, double-buffered smem.
// (unchanged — 243us measured)
// ===========================================================================
#define CH 2176   // 16*136 floats per stage buffer

__global__ __launch_bounds__(256) void qkv_gemm(
    const float* __restrict__ X,
    const float* __restrict__ Wq, const float* __restrict__ bq,
    const float* __restrict__ Wk, const float* __restrict__ bk,
    const float* __restrict__ Wv, const float* __restrict__ bv)
{
    __shared__ float As[2 * CH];   // [buf][k][m], stride 136
    __shared__ float Bs[2 * CH];   // [buf][k][n]

    const float* W; const float* bias;
    if (blockIdx.z == 0)      { W = Wq; bias = bq; }
    else if (blockIdx.z == 1) { W = Wk; bias = bk; }
    else                      { W = Wv; bias = bv; }

    const int tid = threadIdx.x;
    const int wid = tid >> 5, lane = tid & 31, lr = lane >> 2, lc = lane & 3;
    const int wm = wid >> 1, wn = wid & 1;
    const int m0 = blockIdx.y * 128, n0 = blockIdx.x * 128;

    const int arow = tid >> 1, acol = (tid & 1) * 8;
    const int brow = tid >> 4, bcol = (tid & 15) * 8;

    float4 acc[2][8];
    #pragma unroll
    for (int mt = 0; mt < 2; mt++)
        #pragma unroll
        for (int nt = 0; nt < 8; nt++) acc[mt][nt] = make_float4(0.f, 0.f, 0.f, 0.f);

    const float* xp = X + (size_t)(m0 + arow) * DD + acol;
    const float* wp = W + (size_t)brow * DD + n0 + bcol;
    float4 xa0 = *(const float4*)(xp);
    float4 xa1 = *(const float4*)(xp + 4);
    float4 wb0 = *(const float4*)(wp);
    float4 wb1 = *(const float4*)(wp + 4);

    uint32_t* Asu = (uint32_t*)As;
    uint32_t* Bsu = (uint32_t*)Bs;

    {
        float* Ab = As; float* Bb = Bs;
        Ab[(acol + 0) * 136 + arow] = tf32r(xa0.x);
        Ab[(acol + 1) * 136 + arow] = tf32r(xa0.y);
        Ab[(acol + 2) * 136 + arow] = tf32r(xa0.z);
        Ab[(acol + 3) * 136 + arow] = tf32r(xa0.w);
        Ab[(acol + 4) * 136 + arow] = tf32r(xa1.x);
        Ab[(acol + 5) * 136 + arow] = tf32r(xa1.y);
        Ab[(acol + 6) * 136 + arow] = tf32r(xa1.z);
        Ab[(acol + 7) * 136 + arow] = tf32r(xa1.w);
        float4 t0 = make_float4(tf32r(wb0.x), tf32r(wb0.y), tf32r(wb0.z), tf32r(wb0.w));
        float4 t1 = make_float4(tf32r(wb1.x), tf32r(wb1.y), tf32r(wb1.z), tf32r(wb1.w));
        *(float4*)&Bb[brow * 136 + bcol]     = t0;
        *(float4*)&Bb[brow * 136 + bcol + 4] = t1;
    }
    __syncthreads();

    for (int k0 = 0; k0 < DD; k0 += 16) {
        const int cur = (k0 >> 4) & 1;
        const bool haveNext = (k0 + 16) < DD;
        if (haveNext) {
            xa0 = *(const float4*)(xp + k0 + 16);
            xa1 = *(const float4*)(xp + k0 + 20);
            wb0 = *(const float4*)(wp + (size_t)(k0 + 16) * DD);
            wb1 = *(const float4*)(wp + (size_t)(k0 + 16) * DD + 4);
        }

        const uint32_t* Ac = Asu + cur * CH;
        const uint32_t* Bc = Bsu + cur * CH;
        #pragma unroll
        for (int kc = 0; kc < 16; kc += 8) {
            uint32_t a[2][4];
            #pragma unroll
            for (int mt = 0; mt < 2; mt++) {
                const int mb = wm * 32 + mt * 16;
                a[mt][0] = Ac[(kc + lc)     * 136 + mb + lr];
                a[mt][1] = Ac[(kc + lc)     * 136 + mb + lr + 8];
                a[mt][2] = Ac[(kc + lc + 4) * 136 + mb + lr];
                a[mt][3] = Ac[(kc + lc + 4) * 136 + mb + lr + 8];
            }
            #pragma unroll
            for (int nt = 0; nt < 8; nt++) {
                const int nb = wn * 64 + nt * 8;
                uint32_t b0 = Bc[(kc + lc)     * 136 + nb + lr];
                uint32_t b1 = Bc[(kc + lc + 4) * 136 + nb + lr];
                mma8(acc[0][nt], a[0][0], a[0][1], a[0][2], a[0][3], b0, b1);
                mma8(acc[1][nt], a[1][0], a[1][1], a[1][2], a[1][3], b0, b1);
            }
        }

        if (haveNext) {
            float* Ab = As + (cur ^ 1) * CH;
            float* Bb = Bs + (cur ^ 1) * CH;
            Ab[(acol + 0) * 136 + arow] = tf32r(xa0.x);
            Ab[(acol + 1) * 136 + arow] = tf32r(xa0.y);
            Ab[(acol + 2) * 136 + arow] = tf32r(xa0.z);
            Ab[(acol + 3) * 136 + arow] = tf32r(xa0.w);
            Ab[(acol + 4) * 136 + arow] = tf32r(xa1.x);
            Ab[(acol + 5) * 136 + arow] = tf32r(xa1.y);
            Ab[(acol + 6) * 136 + arow] = tf32r(xa1.z);
            Ab[(acol + 7) * 136 + arow] = tf32r(xa1.w);
            float4 t0 = make_float4(tf32r(wb0.x), tf32r(wb0.y), tf32r(wb0.z), tf32r(wb0.w));
            float4 t1 = make_float4(tf32r(wb1.x), tf32r(wb1.y), tf32r(wb1.z), tf32r(wb1.w));
            *(float4*)&Bb[brow * 136 + bcol]     = t0;
            *(float4*)&Bb[brow * 136 + bcol + 4] = t1;
        }
        __syncthreads();
    }

    if (blockIdx.z != 2) {
        float* out = (blockIdx.z == 0) ? g_q : g_k;
        #pragma unroll
        for (int mt = 0; mt < 2; mt++) {
            const int mA = m0 + wm * 32 + mt * 16 + lr;
            const int mB = mA + 8;
            #pragma unroll
            for (int nt = 0; nt < 8; nt++) {
                const int n = n0 + wn * 64 + nt * 8 + 2 * lc;
                const float b0v = __ldg(&bias[n]), b1v = __ldg(&bias[n + 1]);
                const int hh = n >> 6, dd = n & 63;
                {
                    const int bidx = mA >> 11, s = mA & 2047;
                    float2 v; v.x = tf32r(acc[mt][nt].x + b0v); v.y = tf32r(acc[mt][nt].y + b1v);
                    *(float2*)&out[(((size_t)(bidx * NH + hh)) * SQ + s) * HD + dd] = v;
                }
                {
                    const int bidx = mB >> 11, s = mB & 2047;
                    float2 v; v.x = tf32r(acc[mt][nt].z + b0v); v.y = tf32r(acc[mt][nt].w + b1v);
                    *(float2*)&out[(((size_t)(bidx * NH + hh)) * SQ + s) * HD + dd] = v;
                }
            }
        }
    } else {
        #pragma unroll
        for (int mt = 0; mt < 2; mt++) {
            const int mA = m0 + wm * 32 + mt * 16 + lr;
            const int mB = mA + 8;
            const int bA = mA >> 11, sA = mA & 2047;
            const int bB = mB >> 11, sB = mB & 2047;
            #pragma unroll
            for (int nt = 0; nt < 8; nt++) {
                const int n = n0 + wn * 64 + nt * 8 + 2 * lc;
                const float b0v = __ldg(&bias[n]), b1v = __ldg(&bias[n + 1]);
                const int hh = n >> 6, dd = n & 63;
                const size_t base0 = ((size_t)(bA * NH + hh) * HD + dd) * SQ;
                const size_t base1 = ((size_t)(bB * NH + hh) * HD + dd) * SQ;
                g_vt[base0 + sA]       = tf32r(acc[mt][nt].x + b0v);
                g_vt[base0 + SQ + sA]  = tf32r(acc[mt][nt].y + b1v);
                g_vt[base1 + sB]       = tf32r(acc[mt][nt].z + b0v);
                g_vt[base1 + SQ + sB]  = tf32r(acc[mt][nt].w + b1v);
            }
        }
    }
}

// ===========================================================================
// Kernel 2: qrel (unchanged)
// ===========================================================================
__global__ __launch_bounds__(128) void qrel_kernel(const float* __restrict__ emb_k)
{
    __shared__ float ek[NREL * 68];
    const int tid = threadIdx.x;
    const int bh = blockIdx.y, q0 = blockIdx.x * 16;

    for (int idx = tid; idx < NREL * 16; idx += 128) {
        const int r = idx >> 4, d4 = (idx & 15) << 2;
        *(float4*)&ek[r * 68 + d4] = *(const float4*)&emb_k[r * HD + d4];
    }

    const int qi = tid >> 3;
    const int rg = tid & 7;
    float4 qreg[16];
    const float* qp = g_q + (size_t)(bh * SQ + q0 + qi) * HD;
    #pragma unroll
    for (int u = 0; u < 16; u++) qreg[u] = *(const float4*)&qp[u * 4];
    __syncthreads();

    float* orow = g_qrel + (size_t)(bh * SQ + q0 + qi) * QRS;
    for (int r = rg; r < NREL; r += 8) {
        const float* er = ek + r * 68;
        float s = 0.f;
        #pragma unroll
        for (int u = 0; u < 16; u++) {
            float4 e = *(const float4*)&er[u * 4];
            s += qreg[u].x * e.x + qreg[u].y * e.y + qreg[u].z * e.z + qreg[u].w * e.w;
        }
        orow[r] = s;
    }
}

// ===========================================================================
// Kernel 3: flash attention, tf32 mma, no-max softmax, P-in-registers.
// Column permutation trick: mma k-slot lc holds column 2lc (slot lc+4 holds
// 2lc+1), so (x,z,y,w) of a QK output fragment IS the PV A-fragment, and all
// B-fragments become adjacent-pair LDS.64. pw histogram accumulates raw p.
// smem: Ks[64*68] Vt[64*68] pw[128*136] msk[64] = 104.7KB -> 2 CTAs/SM.
// ===========================================================================
#define ATTN_SMEM_BYTES ((4352 + 4352 + 17408 + 64) * 4)
#define C1LOG2E 0.18033688011112042f    // 0.125 * log2(e)
#define LOG2E   1.4426950408889634f

__global__ __launch_bounds__(256, 2) void attn_tf32(
    const float* __restrict__ mask,
    const float* __restrict__ emb_v,
    float* __restrict__ out)
{
    extern __shared__ float sm[];
    float* Ks  = sm;              // [64][68]
    float* Vt  = sm + 4352;       // [64(d)][68(s)]
    float* pw  = sm + 8704;       // [128][136]
    float* msk = sm + 26112;      // [64] (premultiplied by log2e)
    uint32_t* Ksu = (uint32_t*)Ks;
    uint32_t* Vtu = (uint32_t*)Vt;

    const int tid = threadIdx.x;
    const int wid = tid >> 5, lane = tid & 31, lr = lane >> 2, lc = lane & 3;
    const int bh = blockIdx.y, b = bh >> 4, h = bh & 15;
    const int q0 = blockIdx.x * 128;
    const int r0w = wid * 16;
    const int rowA = r0w + lr, rowB = rowA + 8;

    for (int i = lane; i < 16 * 136; i += 32) pw[r0w * 136 + i] = 0.f;

    // Q fragments in registers, k-slots permuted: slot lc <- col 2lc,
    // slot lc+4 <- col 2lc+1 (within each 8-col group).
    uint32_t qreg[8][4];
    {
        const float* qpA = g_q + (size_t)(bh * SQ + q0 + rowA) * HD;
        const float* qpB = qpA + (size_t)8 * HD;
        #pragma unroll
        for (int kc = 0; kc < 8; kc++) {
            qreg[kc][0] = __float_as_uint(qpA[kc * 8 + 2 * lc]);
            qreg[kc][1] = __float_as_uint(qpB[kc * 8 + 2 * lc]);
            qreg[kc][2] = __float_as_uint(qpA[kc * 8 + 2 * lc + 1]);
            qreg[kc][3] = __float_as_uint(qpB[kc * 8 + 2 * lc + 1]);
        }
    }
    const float* qrA = g_qrel + ((size_t)bh * SQ + q0 + rowA) * QRS;
    const float* qrB = g_qrel + ((size_t)bh * SQ + q0 + rowB) * QRS;
    const float rb0A = qrA[0], rb1A = qrA[128];
    const float rb0B = qrB[0], rb1B = qrB[128];

    float l_a = 0.f, l_b = 0.f;
    float h0A = 0.f, h1A = 0.f, h0B = 0.f, h1B = 0.f;
    float4 acc[8];
    #pragma unroll
    for (int nt = 0; nt < 8; nt++) acc[nt] = make_float4(0.f, 0.f, 0.f, 0.f);

    for (int k0 = 0; k0 < SQ; k0 += 64) {
        __syncthreads();   // previous tile fully consumed
        {
            const int row = tid >> 2, c16 = (tid & 3) * 16;
            const float* kp = g_k  + (size_t)(bh * SQ + k0 + row) * HD + c16;
            const float* vp = g_vt + ((size_t)bh * HD + row) * SQ + k0 + c16;
            #pragma unroll
            for (int u = 0; u < 4; u++) {
                *(float4*)&Ks[row * 68 + c16 + u * 4] = *(const float4*)(kp + u * 4);
                *(float4*)&Vt[row * 68 + c16 + u * 4] = *(const float4*)(vp + u * 4);
            }
        }
        if (tid < 64) msk[tid] = mask[(size_t)b * SQ + k0 + tid] * LOG2E;
        __syncthreads();

        const int diff = q0 - k0;
        const bool nearT = (diff >= -128) && (diff <= 64);
        const int delta = diff + 64;

        // ---- scores: S = Q K^T (permuted k-slots; B-frags are LDS.64) ----
        float4 sc4[8];
        #pragma unroll
        for (int nt = 0; nt < 8; nt++) sc4[nt] = make_float4(0.f, 0.f, 0.f, 0.f);
        #pragma unroll
        for (int kc = 0; kc < 8; kc++) {
            #pragma unroll
            for (int nt = 0; nt < 8; nt++) {
                const uint2 kb = *(const uint2*)&Ksu[(nt * 8 + lr) * 68 + kc * 8 + 2 * lc];
                mma8(sc4[nt], qreg[kc][0], qreg[kc][1], qreg[kc][2], qreg[kc][3], kb.x, kb.y);
            }
        }

        // ---- bias + mask + scale (log2 domain) ----
        if (nearT) {
            #pragma unroll
            for (int nt = 0; nt < 8; nt++) {
                const int c0 = nt * 8 + 2 * lc;
                const float2 mk = *(const float2*)&msk[c0];
                const int bA = rowA + delta - c0;
                const int bB = rowB + delta - c0;
                const int bAx = min(max(bA, 0), 128),     bAy = min(max(bA - 1, 0), 128);
                const int bBx = min(max(bB, 0), 128),     bBy = min(max(bB - 1, 0), 128);
                sc4[nt].x = (sc4[nt].x + __ldg(&qrA[bAx])) * C1LOG2E + mk.x;
                sc4[nt].y = (sc4[nt].y + __ldg(&qrA[bAy])) * C1LOG2E + mk.y;
                sc4[nt].z = (sc4[nt].z + __ldg(&qrB[bBx])) * C1LOG2E + mk.x;
                sc4[nt].w = (sc4[nt].w + __ldg(&qrB[bBy])) * C1LOG2E + mk.y;
            }
        } else {
            const float rbA = (diff > 0) ? rb1A : rb0A;
            const float rbB = (diff > 0) ? rb1B : rb0B;
            #pragma unroll
            for (int nt = 0; nt < 8; nt++) {
                const int c0 = nt * 8 + 2 * lc;
                const float2 mk = *(const float2*)&msk[c0];
                sc4[nt].x = (sc4[nt].x + rbA) * C1LOG2E + mk.x;
                sc4[nt].y = (sc4[nt].y + rbA) * C1LOG2E + mk.y;
                sc4[nt].z = (sc4[nt].z + rbB) * C1LOG2E + mk.x;
                sc4[nt].w = (sc4[nt].w + rbB) * C1LOG2E + mk.y;
            }
        }

        // ---- p = 2^s (no-max: scores bounded), partial row sums ----
        float psA = 0.f, psB = 0.f;
        #pragma unroll
        for (int nt = 0; nt < 8; nt++) {
            sc4[nt].x = ex2f(sc4[nt].x); psA += sc4[nt].x;
            sc4[nt].y = ex2f(sc4[nt].y); psA += sc4[nt].y;
            sc4[nt].z = ex2f(sc4[nt].z); psB += sc4[nt].z;
            sc4[nt].w = ex2f(sc4[nt].w); psB += sc4[nt].w;
        }

        // ---- rel-V histogram (raw p) ----
        if (!nearT) {
            if (diff > 0) { h1A += psA; h1B += psB; }
            else          { h0A += psA; h0B += psB; }
        } else {
            #pragma unroll
            for (int nt = 0; nt < 8; nt++) {
                const int c0 = nt * 8 + 2 * lc;
                const int bA = rowA + delta - c0;
                const int bB = rowB + delta - c0;
                if (bA >= 128) h1A += sc4[nt].x; else if (bA <= 0) h0A += sc4[nt].x; else pw[rowA * 136 + bA] += sc4[nt].x;
                if (bA - 1 >= 128) h1A += sc4[nt].y; else if (bA - 1 <= 0) h0A += sc4[nt].y; else pw[rowA * 136 + bA - 1] += sc4[nt].y;
                if (bB >= 128) h1B += sc4[nt].z; else if (bB <= 0) h0B += sc4[nt].z; else pw[rowB * 136 + bB] += sc4[nt].z;
                if (bB - 1 >= 128) h1B += sc4[nt].w; else if (bB - 1 <= 0) h0B += sc4[nt].w; else pw[rowB * 136 + bB - 1] += sc4[nt].w;
            }
        }

        psA += __shfl_xor_sync(0xffffffffu, psA, 1);
        psA += __shfl_xor_sync(0xffffffffu, psA, 2);
        psB += __shfl_xor_sync(0xffffffffu, psB, 1);
        psB += __shfl_xor_sync(0xffffffffu, psB, 2);
        l_a += psA; l_b += psB;

        // ---- acc += P @ V: A-frags straight from sc4 registers (x,z,y,w);
        //      permuted k-slots make Vt B-frags adjacent LDS.64 ----
        #pragma unroll
        for (int kc = 0; kc < 8; kc++) {
            const uint32_t a0 = tf32b(sc4[kc].x);
            const uint32_t a1 = tf32b(sc4[kc].z);
            const uint32_t a2 = tf32b(sc4[kc].y);
            const uint32_t a3 = tf32b(sc4[kc].w);
            #pragma unroll
            for (int nt = 0; nt < 8; nt++) {
                const uint2 vb = *(const uint2*)&Vtu[(nt * 8 + lr) * 68 + kc * 8 + 2 * lc];
                mma8(acc[nt], a0, a1, a2, a3, vb.x, vb.y);
            }
        }
    }

    // ---- fold edge-bucket registers into pw (rows warp-private) ----
    h0A += __shfl_xor_sync(0xffffffffu, h0A, 1);
    h0A += __shfl_xor_sync(0xffffffffu, h0A, 2);
    h1A += __shfl_xor_sync(0xffffffffu, h1A, 1);
    h1A += __shfl_xor_sync(0xffffffffu, h1A, 2);
    h0B += __shfl_xor_sync(0xffffffffu, h0B, 1);
    h0B += __shfl_xor_sync(0xffffffffu, h0B, 2);
    h1B += __shfl_xor_sync(0xffffffffu, h1B, 1);
    h1B += __shfl_xor_sync(0xffffffffu, h1B, 2);
    if (lc == 0) {
        pw[rowA * 136 + 0]   += h0A;
        pw[rowA * 136 + 128] += h1A;
        pw[rowB * 136 + 0]   += h0B;
        pw[rowB * 136 + 128] += h1B;
    }
    __syncthreads();

    // ---- epilogue: evt = emb_v^T [d][136] overlays Ks+Vt; racc = pw @ evt ----
    float* evt = sm;
    uint32_t* evtu = (uint32_t*)evt;
    for (int idx = tid; idx < NREL * HD; idx += 256) {
        const int r = idx >> 6, d = idx & 63;
        evt[d * 136 + r] = tf32r(emb_v[idx]);
    }
    if (tid < 64) {
        #pragma unroll
        for (int r = NREL; r < 136; r++) evt[tid * 136 + r] = 0.f;
    }
    __syncthreads();

    float4 racc[8];
    #pragma unroll
    for (int nt = 0; nt < 8; nt++) racc[nt] = make_float4(0.f, 0.f, 0.f, 0.f);
    #pragma unroll
    for (int kc = 0; kc < 136; kc += 8) {
        const uint32_t a0 = tf32b(pw[rowA * 136 + kc + lc]);
        const uint32_t a1 = tf32b(pw[(rowA + 8) * 136 + kc + lc]);
        const uint32_t a2 = tf32b(pw[rowA * 136 + kc + lc + 4]);
        const uint32_t a3 = tf32b(pw[(rowA + 8) * 136 + kc + lc + 4]);
        #pragma unroll
        for (int nt = 0; nt < 8; nt++) {
            const uint32_t b0 = evtu[(nt * 8 + lr) * 136 + kc + lc];
            const uint32_t b1 = evtu[(nt * 8 + lr) * 136 + kc + lc + 4];
            mma8(racc[nt], a0, a1, a2, a3, b0, b1);
        }
    }

    // ---- out = (acc + racc) / l, direct float2 stores ----
    const float rlA = 1.f / l_a, rlB = 1.f / l_b;
    float* opA = out + ((size_t)(b * SQ + q0 + rowA)) * DD + h * HD;
    float* opB = out + ((size_t)(b * SQ + q0 + rowB)) * DD + h * HD;
    #pragma unroll
    for (int nt = 0; nt < 8; nt++) {
        const int c0 = nt * 8 + 2 * lc;
        float2 oa;
        oa.x = (acc[nt].x + racc[nt].x) * rlA;
        oa.y = (acc[nt].y + racc[nt].y) * rlA;
        *(float2*)&opA[c0] = oa;
        float2 ob;
        ob.x = (acc[nt].z + racc[nt].z) * rlB;
        ob.y = (acc[nt].w + racc[nt].w) * rlB;
        *(float2*)&opB[c0] = ob;
    }
}

// ===========================================================================
extern "C" void kernel_launch(void* const* d_in, const int* in_sizes, int n_in,
                              void* d_out, int out_size)
{
    const float* hidden = (const float*)d_in[0];
    const float* mask   = (const float*)d_in[1];
    const float* Wq     = (const float*)d_in[2];
    const float* bq     = (const float*)d_in[3];
    const float* Wk     = (const float*)d_in[4];
    const float* bk     = (const float*)d_in[5];
    const float* Wv     = (const float*)d_in[6];
    const float* bv     = (const float*)d_in[7];
    const float* emb_k  = (const float*)d_in[8];
    const float* emb_v  = (const float*)d_in[9];
    float* out = (float*)d_out;

    dim3 g1(DD / 128, (BB * SQ) / 128, 3);
    qkv_gemm<<<g1, 256>>>(hidden, Wq, bq, Wk, bk, Wv, bv);

    dim3 g2(SQ / 16, BH);
    qrel_kernel<<<g2, 128>>>(emb_k);

    cudaFuncSetAttribute(attn_tf32, cudaFuncAttributeMaxDynamicSharedMemorySize,
                         ATTN_SMEM_BYTES);
    dim3 g3(SQ / 128, BH);
    attn_tf32<<<g3, 256, ATTN_SMEM_BYTES>>>(mask, emb_v, out);
}

// round 8
// speedup vs baseline: 3.2820x; 1.4386x over previous
#include <cuda_runtime.h>
#include <cuda_fp16.h>
#include <cstdint>

#define BB   2
#define SQ   2048
#define DD   1024
#define NH   16
#define HD   64
#define BH   (BB*NH)      // 32
#define NREL 129
#define QRS  132          // qrel row stride (padded)

// ---------------- scratch (device globals: sanctioned workaround) ----------
__device__ __half g_qh[(size_t)BH * SQ * HD];    // [bh][s][d]  fp16, natural cols
__device__ __half g_kh[(size_t)BH * SQ * HD];    // [bh][s][d]  fp16, pair-permuted d
__device__ __half g_vth[(size_t)BH * HD * SQ];   // [bh][d][s]  fp16, pair-permuted s
__device__ float  g_qrel[(size_t)BH * SQ * QRS]; // [bh][q][129 (pad 132)] fp32

// ---------------- helpers --------------------------------------------------
__device__ __forceinline__ float tf32r(float x) {
    uint32_t u; asm("cvt.rna.tf32.f32 %0, %1;" : "=r"(u) : "f"(x));
    return __uint_as_float(u);
}
__device__ __forceinline__ float ex2f(float x) {
    float r; asm("ex2.approx.f32 %0, %1;" : "=f"(r) : "f"(x));
    return r;
}
__device__ __forceinline__ uint32_t h2b(float lo, float hi) {
    __half2 h = __floats2half2_rn(lo, hi);
    return *(uint32_t*)&h;
}
// pair-interleave permutation within 16-element blocks:
// pair j (j<4) -> stored pos 2j ; pair j (j>=4) -> stored pos 2(j-4)+1
__device__ __forceinline__ int sperm(int s) {
    int j = (s >> 1) & 7;
    return (s & ~15) + ((((j & 3) << 1) | (j >> 2)) << 1) + (s & 1);
}
// legacy tf32 k8 mma (qkv projection)
__device__ __forceinline__ void mma8(float4& d,
                                     uint32_t a0, uint32_t a1, uint32_t a2, uint32_t a3,
                                     uint32_t b0, uint32_t b1) {
    asm("mma.sync.aligned.m16n8k8.row.col.f32.tf32.tf32.f32 "
        "{%0,%1,%2,%3},{%4,%5,%6,%7},{%8,%9},{%0,%1,%2,%3};"
        : "+f"(d.x), "+f"(d.y), "+f"(d.z), "+f"(d.w)
        : "r"(a0), "r"(a1), "r"(a2), "r"(a3), "r"(b0), "r"(b1));
}
// fp16 k16 mma (attention)
__device__ __forceinline__ void mma16(float4& d,
                                      uint32_t a0, uint32_t a1, uint32_t a2, uint32_t a3,
                                      uint32_t b0, uint32_t b1) {
    asm("mma.sync.aligned.m16n8k16.row.col.f32.f16.f16.f32 "
        "{%0,%1,%2,%3},{%4,%5,%6,%7},{%8,%9},{%0,%1,%2,%3};"
        : "+f"(d.x), "+f"(d.y), "+f"(d.z), "+f"(d.w)
        : "r"(a0), "r"(a1), "r"(a2), "r"(a3), "r"(b0), "r"(b1));
}

// ===========================================================================
// Kernel 1: fused QKV projection via tf32 mma, double-buffered smem.
// Mainloop unchanged (242us measured). Epilogue now emits fp16:
//   Q natural; K with pair-permuted d columns; V^T with pair-permuted s.
// ===========================================================================
#define CH 2176   // 16*136 floats per stage buffer

__global__ __launch_bounds__(256) void qkv_gemm(
    const float* __restrict__ X,
    const float* __restrict__ Wq, const float* __restrict__ bq,
    const float* __restrict__ Wk, const float* __restrict__ bk,
    const float* __restrict__ Wv, const float* __restrict__ bv)
{
    __shared__ float As[2 * CH];
    __shared__ float Bs[2 * CH];

    const float* W; const float* bias;
    if (blockIdx.z == 0)      { W = Wq; bias = bq; }
    else if (blockIdx.z == 1) { W = Wk; bias = bk; }
    else                      { W = Wv; bias = bv; }

    const int tid = threadIdx.x;
    const int wid = tid >> 5, lane = tid & 31, lr = lane >> 2, lc = lane & 3;
    const int wm = wid >> 1, wn = wid & 1;
    const int m0 = blockIdx.y * 128, n0 = blockIdx.x * 128;

    const int arow = tid >> 1, acol = (tid & 1) * 8;
    const int brow = tid >> 4, bcol = (tid & 15) * 8;

    float4 acc[2][8];
    #pragma unroll
    for (int mt = 0; mt < 2; mt++)
        #pragma unroll
        for (int nt = 0; nt < 8; nt++) acc[mt][nt] = make_float4(0.f, 0.f, 0.f, 0.f);

    const float* xp = X + (size_t)(m0 + arow) * DD + acol;
    const float* wp = W + (size_t)brow * DD + n0 + bcol;
    float4 xa0 = *(const float4*)(xp);
    float4 xa1 = *(const float4*)(xp + 4);
    float4 wb0 = *(const float4*)(wp);
    float4 wb1 = *(const float4*)(wp + 4);

    uint32_t* Asu = (uint32_t*)As;
    uint32_t* Bsu = (uint32_t*)Bs;

    {
        float* Ab = As; float* Bb = Bs;
        Ab[(acol + 0) * 136 + arow] = tf32r(xa0.x);
        Ab[(acol + 1) * 136 + arow] = tf32r(xa0.y);
        Ab[(acol + 2) * 136 + arow] = tf32r(xa0.z);
        Ab[(acol + 3) * 136 + arow] = tf32r(xa0.w);
        Ab[(acol + 4) * 136 + arow] = tf32r(xa1.x);
        Ab[(acol + 5) * 136 + arow] = tf32r(xa1.y);
        Ab[(acol + 6) * 136 + arow] = tf32r(xa1.z);
        Ab[(acol + 7) * 136 + arow] = tf32r(xa1.w);
        float4 t0 = make_float4(tf32r(wb0.x), tf32r(wb0.y), tf32r(wb0.z), tf32r(wb0.w));
        float4 t1 = make_float4(tf32r(wb1.x), tf32r(wb1.y), tf32r(wb1.z), tf32r(wb1.w));
        *(float4*)&Bb[brow * 136 + bcol]     = t0;
        *(float4*)&Bb[brow * 136 + bcol + 4] = t1;
    }
    __syncthreads();

    for (int k0 = 0; k0 < DD; k0 += 16) {
        const int cur = (k0 >> 4) & 1;
        const bool haveNext = (k0 + 16) < DD;
        if (haveNext) {
            xa0 = *(const float4*)(xp + k0 + 16);
            xa1 = *(const float4*)(xp + k0 + 20);
            wb0 = *(const float4*)(wp + (size_t)(k0 + 16) * DD);
            wb1 = *(const float4*)(wp + (size_t)(k0 + 16) * DD + 4);
        }

        const uint32_t* Ac = Asu + cur * CH;
        const uint32_t* Bc = Bsu + cur * CH;
        #pragma unroll
        for (int kc = 0; kc < 16; kc += 8) {
            uint32_t a[2][4];
            #pragma unroll
            for (int mt = 0; mt < 2; mt++) {
                const int mb = wm * 32 + mt * 16;
                a[mt][0] = Ac[(kc + lc)     * 136 + mb + lr];
                a[mt][1] = Ac[(kc + lc)     * 136 + mb + lr + 8];
                a[mt][2] = Ac[(kc + lc + 4) * 136 + mb + lr];
                a[mt][3] = Ac[(kc + lc + 4) * 136 + mb + lr + 8];
            }
            #pragma unroll
            for (int nt = 0; nt < 8; nt++) {
                const int nb = wn * 64 + nt * 8;
                uint32_t b0 = Bc[(kc + lc)     * 136 + nb + lr];
                uint32_t b1 = Bc[(kc + lc + 4) * 136 + nb + lr];
                mma8(acc[0][nt], a[0][0], a[0][1], a[0][2], a[0][3], b0, b1);
                mma8(acc[1][nt], a[1][0], a[1][1], a[1][2], a[1][3], b0, b1);
            }
        }

        if (haveNext) {
            float* Ab = As + (cur ^ 1) * CH;
            float* Bb = Bs + (cur ^ 1) * CH;
            Ab[(acol + 0) * 136 + arow] = tf32r(xa0.x);
            Ab[(acol + 1) * 136 + arow] = tf32r(xa0.y);
            Ab[(acol + 2) * 136 + arow] = tf32r(xa0.z);
            Ab[(acol + 3) * 136 + arow] = tf32r(xa0.w);
            Ab[(acol + 4) * 136 + arow] = tf32r(xa1.x);
            Ab[(acol + 5) * 136 + arow] = tf32r(xa1.y);
            Ab[(acol + 6) * 136 + arow] = tf32r(xa1.z);
            Ab[(acol + 7) * 136 + arow] = tf32r(xa1.w);
            float4 t0 = make_float4(tf32r(wb0.x), tf32r(wb0.y), tf32r(wb0.z), tf32r(wb0.w));
            float4 t1 = make_float4(tf32r(wb1.x), tf32r(wb1.y), tf32r(wb1.z), tf32r(wb1.w));
            *(float4*)&Bb[brow * 136 + bcol]     = t0;
            *(float4*)&Bb[brow * 136 + bcol + 4] = t1;
        }
        __syncthreads();
    }

    // ---- epilogue: add bias, convert fp16, scatter ----
    if (blockIdx.z == 0) {
        // Q: natural columns
        #pragma unroll
        for (int mt = 0; mt < 2; mt++) {
            const int mA = m0 + wm * 32 + mt * 16 + lr;
            const int mB = mA + 8;
            #pragma unroll
            for (int nt = 0; nt < 8; nt++) {
                const int n = n0 + wn * 64 + nt * 8 + 2 * lc;
                const float b0v = __ldg(&bias[n]), b1v = __ldg(&bias[n + 1]);
                const int hh = n >> 6, dd = n & 63;
                {
                    const int bidx = mA >> 11, s = mA & 2047;
                    *(__half2*)&g_qh[(((size_t)(bidx * NH + hh)) * SQ + s) * HD + dd] =
                        __floats2half2_rn(acc[mt][nt].x + b0v, acc[mt][nt].y + b1v);
                }
                {
                    const int bidx = mB >> 11, s = mB & 2047;
                    *(__half2*)&g_qh[(((size_t)(bidx * NH + hh)) * SQ + s) * HD + dd] =
                        __floats2half2_rn(acc[mt][nt].z + b0v, acc[mt][nt].w + b1v);
                }
            }
        }
    } else if (blockIdx.z == 1) {
        // K: pair-permuted d columns
        #pragma unroll
        for (int mt = 0; mt < 2; mt++) {
            const int mA = m0 + wm * 32 + mt * 16 + lr;
            const int mB = mA + 8;
            #pragma unroll
            for (int nt = 0; nt < 8; nt++) {
                const int n = n0 + wn * 64 + nt * 8 + 2 * lc;
                const float b0v = __ldg(&bias[n]), b1v = __ldg(&bias[n + 1]);
                const int hh = n >> 6, dd = n & 63;
                const int pc = sperm(dd);   // dd even -> parity 0
                {
                    const int bidx = mA >> 11, s = mA & 2047;
                    *(__half2*)&g_kh[(((size_t)(bidx * NH + hh)) * SQ + s) * HD + pc] =
                        __floats2half2_rn(acc[mt][nt].x + b0v, acc[mt][nt].y + b1v);
                }
                {
                    const int bidx = mB >> 11, s = mB & 2047;
                    *(__half2*)&g_kh[(((size_t)(bidx * NH + hh)) * SQ + s) * HD + pc] =
                        __floats2half2_rn(acc[mt][nt].z + b0v, acc[mt][nt].w + b1v);
                }
            }
        }
    } else {
        // V: transposed scatter [bh][d][s], pair-permuted s columns
        #pragma unroll
        for (int mt = 0; mt < 2; mt++) {
            const int mA = m0 + wm * 32 + mt * 16 + lr;
            const int mB = mA + 8;
            const int bA = mA >> 11, sA = mA & 2047;
            const int bB = mB >> 11, sB = mB & 2047;
            const int pA = sperm(sA), pB = sperm(sB);
            #pragma unroll
            for (int nt = 0; nt < 8; nt++) {
                const int n = n0 + wn * 64 + nt * 8 + 2 * lc;
                const float b0v = __ldg(&bias[n]), b1v = __ldg(&bias[n + 1]);
                const int hh = n >> 6, dd = n & 63;
                const size_t base0 = ((size_t)(bA * NH + hh) * HD + dd) * SQ;
                const size_t base1 = ((size_t)(bB * NH + hh) * HD + dd) * SQ;
                g_vth[base0 + pA]      = __float2half_rn(acc[mt][nt].x + b0v);
                g_vth[base0 + SQ + pA] = __float2half_rn(acc[mt][nt].y + b1v);
                g_vth[base1 + pB]      = __float2half_rn(acc[mt][nt].z + b0v);
                g_vth[base1 + SQ + pB] = __float2half_rn(acc[mt][nt].w + b1v);
            }
        }
    }
}

// ===========================================================================
// Kernel 2: qrel[bh][q][r] = Q . emb_k[r]  (Q now fp16, math fp32)
// ===========================================================================
__global__ __launch_bounds__(128) void qrel_kernel(const float* __restrict__ emb_k)
{
    __shared__ float ek[NREL * 68];
    const int tid = threadIdx.x;
    const int bh = blockIdx.y, q0 = blockIdx.x * 16;

    for (int idx = tid; idx < NREL * 16; idx += 128) {
        const int r = idx >> 4, d4 = (idx & 15) << 2;
        *(float4*)&ek[r * 68 + d4] = *(const float4*)&emb_k[r * HD + d4];
    }

    const int qi = tid >> 3;
    const int rg = tid & 7;
    float q[64];
    {
        const __half2* qp2 = (const __half2*)(g_qh + (size_t)(bh * SQ + q0 + qi) * HD);
        #pragma unroll
        for (int u = 0; u < 32; u++) {
            float2 f = __half22float2(qp2[u]);
            q[2 * u] = f.x; q[2 * u + 1] = f.y;
        }
    }
    __syncthreads();

    float* orow = g_qrel + (size_t)(bh * SQ + q0 + qi) * QRS;
    for (int r = rg; r < NREL; r += 8) {
        const float* er = ek + r * 68;
        float s = 0.f;
        #pragma unroll
        for (int u = 0; u < 64; u++) s += q[u] * er[u];
        orow[r] = s;
    }
}

// ===========================================================================
// Kernel 3: flash attention, fp16 m16n8k16 mma (2x flops/instr vs tf32 k8).
// No-max softmax (bounded scores), P straight from QK output fragments via
// f16x2 packing; K/V^T pair-permuted in GMEM so every B-frag is one LDS.64
// (row stride 80 halves -> conflict-free). fp32 softmax/hist/accum.
// smem: Ks[64][80]h Vt[64][80]h pw[128][144]f msk[64]f = 94464B -> 2 CTAs/SM
// ===========================================================================
#define PWS 144
#define ATTN_SMEM_BYTES (10240 + 10240 + 128 * PWS * 4 + 256)
#define C1LOG2E 0.18033688011112042f    // 0.125 * log2(e)
#define LOG2E   1.4426950408889634f

__global__ __launch_bounds__(256, 2) void attn_f16(
    const float* __restrict__ mask,
    const float* __restrict__ emb_v,
    float* __restrict__ out)
{
    extern __shared__ char smc[];
    __half* Ks = (__half*)smc;                       // [64][80]
    __half* Vt = (__half*)(smc + 10240);             // [64(d)][80(s)]
    float*  pw = (float*)(smc + 20480);              // [128][144]
    float* msk = (float*)(smc + 20480 + 128 * PWS * 4);

    const int tid = threadIdx.x;
    const int wid = tid >> 5, lane = tid & 31, lr = lane >> 2, lc = lane & 3;
    const int bh = blockIdx.y, b = bh >> 4, h = bh & 15;
    const int q0 = blockIdx.x * 128;
    const int r0w = wid * 16;
    const int rowA = r0w + lr, rowB = rowA + 8;

    for (int i = lane; i < 16 * PWS; i += 32) pw[r0w * PWS + i] = 0.f;

    // Q fragments (fp16 pairs, natural layout) from global — once
    uint32_t qf[4][4];
    {
        const __half* qA = g_qh + ((size_t)bh * SQ + q0 + rowA) * HD;
        const __half* qB = qA + 8 * HD;
        #pragma unroll
        for (int kc = 0; kc < 4; kc++) {
            qf[kc][0] = *(const uint32_t*)&qA[kc * 16 + 2 * lc];
            qf[kc][1] = *(const uint32_t*)&qB[kc * 16 + 2 * lc];
            qf[kc][2] = *(const uint32_t*)&qA[kc * 16 + 2 * lc + 8];
            qf[kc][3] = *(const uint32_t*)&qB[kc * 16 + 2 * lc + 8];
        }
    }
    const float* qrA = g_qrel + ((size_t)bh * SQ + q0 + rowA) * QRS;
    const float* qrB = g_qrel + ((size_t)bh * SQ + q0 + rowB) * QRS;
    const float rb0A = qrA[0], rb1A = qrA[128];
    const float rb0B = qrB[0], rb1B = qrB[128];

    float l_a = 0.f, l_b = 0.f;
    float h0A = 0.f, h1A = 0.f, h0B = 0.f, h1B = 0.f;
    float4 acc[8];
    #pragma unroll
    for (int nt = 0; nt < 8; nt++) acc[nt] = make_float4(0.f, 0.f, 0.f, 0.f);

    for (int k0 = 0; k0 < SQ; k0 += 64) {
        __syncthreads();   // previous tile fully consumed
        {
            const int row = tid >> 2, cq = (tid & 3) * 16;
            const __half* kp = g_kh  + ((size_t)bh * SQ + k0 + row) * HD + cq;
            const __half* vp = g_vth + ((size_t)bh * HD + row) * SQ + k0 + cq;
            *(uint4*)&Ks[row * 80 + cq]     = *(const uint4*)kp;
            *(uint4*)&Ks[row * 80 + cq + 8] = *(const uint4*)(kp + 8);
            *(uint4*)&Vt[row * 80 + cq]     = *(const uint4*)vp;
            *(uint4*)&Vt[row * 80 + cq + 8] = *(const uint4*)(vp + 8);
        }
        if (tid < 64) msk[tid] = mask[(size_t)b * SQ + k0 + tid] * LOG2E;
        __syncthreads();

        const int diff = q0 - k0;
        const bool nearT = (diff >= -128) && (diff <= 64);
        const int delta = diff + 64;

        // ---- scores: S = Q K^T (fp16 k16; B-frags single LDS.64) ----
        float4 sc4[8];
        #pragma unroll
        for (int nt = 0; nt < 8; nt++) sc4[nt] = make_float4(0.f, 0.f, 0.f, 0.f);
        {
            const uint2* K2 = (const uint2*)Ks;
            #pragma unroll
            for (int kc = 0; kc < 4; kc++) {
                #pragma unroll
                for (int nt = 0; nt < 8; nt++) {
                    const uint2 kb = K2[(nt * 8 + lr) * 20 + kc * 4 + lc];
                    mma16(sc4[nt], qf[kc][0], qf[kc][1], qf[kc][2], qf[kc][3], kb.x, kb.y);
                }
            }
        }

        // ---- bias + mask + scale (log2 domain) ----
        if (nearT) {
            #pragma unroll
            for (int nt = 0; nt < 8; nt++) {
                const int c0 = nt * 8 + 2 * lc;
                const float2 mk = *(const float2*)&msk[c0];
                const int bA = rowA + delta - c0;
                const int bB = rowB + delta - c0;
                const int bAx = min(max(bA, 0), 128),     bAy = min(max(bA - 1, 0), 128);
                const int bBx = min(max(bB, 0), 128),     bBy = min(max(bB - 1, 0), 128);
                sc4[nt].x = (sc4[nt].x + __ldg(&qrA[bAx])) * C1LOG2E + mk.x;
                sc4[nt].y = (sc4[nt].y + __ldg(&qrA[bAy])) * C1LOG2E + mk.y;
                sc4[nt].z = (sc4[nt].z + __ldg(&qrB[bBx])) * C1LOG2E + mk.x;
                sc4[nt].w = (sc4[nt].w + __ldg(&qrB[bBy])) * C1LOG2E + mk.y;
            }
        } else {
            const float rbA = (diff > 0) ? rb1A : rb0A;
            const float rbB = (diff > 0) ? rb1B : rb0B;
            #pragma unroll
            for (int nt = 0; nt < 8; nt++) {
                const int c0 = nt * 8 + 2 * lc;
                const float2 mk = *(const float2*)&msk[c0];
                sc4[nt].x = (sc4[nt].x + rbA) * C1LOG2E + mk.x;
                sc4[nt].y = (sc4[nt].y + rbA) * C1LOG2E + mk.y;
                sc4[nt].z = (sc4[nt].z + rbB) * C1LOG2E + mk.x;
                sc4[nt].w = (sc4[nt].w + rbB) * C1LOG2E + mk.y;
            }
        }

        // ---- p = 2^s (bounded scores), partial row sums ----
        float psA = 0.f, psB = 0.f;
        #pragma unroll
        for (int nt = 0; nt < 8; nt++) {
            sc4[nt].x = ex2f(sc4[nt].x); psA += sc4[nt].x;
            sc4[nt].y = ex2f(sc4[nt].y); psA += sc4[nt].y;
            sc4[nt].z = ex2f(sc4[nt].z); psB += sc4[nt].z;
            sc4[nt].w = ex2f(sc4[nt].w); psB += sc4[nt].w;
        }

        // ---- rel-V histogram (fp32 p) ----
        if (!nearT) {
            if (diff > 0) { h1A += psA; h1B += psB; }
            else          { h0A += psA; h0B += psB; }
        } else {
            #pragma unroll
            for (int nt = 0; nt < 8; nt++) {
                const int c0 = nt * 8 + 2 * lc;
                const int bA = rowA + delta - c0;
                const int bB = rowB + delta - c0;
                if (bA >= 128) h1A += sc4[nt].x; else if (bA <= 0) h0A += sc4[nt].x; else pw[rowA * PWS + bA] += sc4[nt].x;
                if (bA - 1 >= 128) h1A += sc4[nt].y; else if (bA - 1 <= 0) h0A += sc4[nt].y; else pw[rowA * PWS + bA - 1] += sc4[nt].y;
                if (bB >= 128) h1B += sc4[nt].z; else if (bB <= 0) h0B += sc4[nt].z; else pw[rowB * PWS + bB] += sc4[nt].z;
                if (bB - 1 >= 128) h1B += sc4[nt].w; else if (bB - 1 <= 0) h0B += sc4[nt].w; else pw[rowB * PWS + bB - 1] += sc4[nt].w;
            }
        }

        psA += __shfl_xor_sync(0xffffffffu, psA, 1);
        psA += __shfl_xor_sync(0xffffffffu, psA, 2);
        psB += __shfl_xor_sync(0xffffffffu, psB, 1);
        psB += __shfl_xor_sync(0xffffffffu, psB, 2);
        l_a += psA; l_b += psB;

        // ---- acc += P @ V: A-frags = packed QK fragments; one LDS.64 B ----
        {
            const uint2* V2 = (const uint2*)Vt;
            #pragma unroll
            for (int kc = 0; kc < 4; kc++) {
                const uint32_t a0 = h2b(sc4[2 * kc].x,     sc4[2 * kc].y);
                const uint32_t a1 = h2b(sc4[2 * kc].z,     sc4[2 * kc].w);
                const uint32_t a2 = h2b(sc4[2 * kc + 1].x, sc4[2 * kc + 1].y);
                const uint32_t a3 = h2b(sc4[2 * kc + 1].z, sc4[2 * kc + 1].w);
                #pragma unroll
                for (int nt = 0; nt < 8; nt++) {
                    const uint2 vb = V2[(nt * 8 + lr) * 20 + kc * 4 + lc];
                    mma16(acc[nt], a0, a1, a2, a3, vb.x, vb.y);
                }
            }
        }
    }

    // ---- fold edge-bucket registers into pw (rows warp-private) ----
    h0A += __shfl_xor_sync(0xffffffffu, h0A, 1);
    h0A += __shfl_xor_sync(0xffffffffu, h0A, 2);
    h1A += __shfl_xor_sync(0xffffffffu, h1A, 1);
    h1A += __shfl_xor_sync(0xffffffffu, h1A, 2);
    h0B += __shfl_xor_sync(0xffffffffu, h0B, 1);
    h0B += __shfl_xor_sync(0xffffffffu, h0B, 2);
    h1B += __shfl_xor_sync(0xffffffffu, h1B, 1);
    h1B += __shfl_xor_sync(0xffffffffu, h1B, 2);
    if (lc == 0) {
        pw[rowA * PWS + 0]   += h0A;
        pw[rowA * PWS + 128] += h1A;
        pw[rowB * PWS + 0]   += h0B;
        pw[rowB * PWS + 128] += h1B;
    }
    __syncthreads();

    // ---- epilogue: evt = emb_v^T fp16 [64(d)][144(r)] overlays Ks+Vt ----
    __half* evt = (__half*)smc;   // 64*144*2 = 18432B <= 20480B
    for (int idx = tid; idx < 64 * PWS; idx += 256) {
        const int d = idx / PWS, r = idx - d * PWS;
        evt[idx] = (r < NREL) ? __float2half_rn(emb_v[r * HD + d]) : __half(0.f);
    }
    __syncthreads();

    float4 racc[8];
    #pragma unroll
    for (int nt = 0; nt < 8; nt++) racc[nt] = make_float4(0.f, 0.f, 0.f, 0.f);
    #pragma unroll
    for (int kc = 0; kc < 9; kc++) {   // k = 144 = 9 * 16
        const int kb = kc * 16 + 2 * lc;
        const uint32_t a0 = h2b(pw[rowA * PWS + kb],     pw[rowA * PWS + kb + 1]);
        const uint32_t a1 = h2b(pw[rowB * PWS + kb],     pw[rowB * PWS + kb + 1]);
        const uint32_t a2 = h2b(pw[rowA * PWS + kb + 8], pw[rowA * PWS + kb + 9]);
        const uint32_t a3 = h2b(pw[rowB * PWS + kb + 8], pw[rowB * PWS + kb + 9]);
        #pragma unroll
        for (int nt = 0; nt < 8; nt++) {
            const uint32_t b0 = *(const uint32_t*)&evt[(nt * 8 + lr) * PWS + kb];
            const uint32_t b1 = *(const uint32_t*)&evt[(nt * 8 + lr) * PWS + kb + 8];
            mma16(racc[nt], a0, a1, a2, a3, b0, b1);
        }
    }

    // ---- out = (acc + racc) / l ----
    const float rlA = 1.f / l_a, rlB = 1.f / l_b;
    float* opA = out + ((size_t)(b * SQ + q0 + rowA)) * DD + h * HD;
    float* opB = out + ((size_t)(b * SQ + q0 + rowB)) * DD + h * HD;
    #pragma unroll
    for (int nt = 0; nt < 8; nt++) {
        const int c0 = nt * 8 + 2 * lc;
        float2 oa;
        oa.x = (acc[nt].x + racc[nt].x) * rlA;
        oa.y = (acc[nt].y + racc[nt].y) * rlA;
        *(float2*)&opA[c0] = oa;
        float2 ob;
        ob.x = (acc[nt].z + racc[nt].z) * rlB;
        ob.y = (acc[nt].w + racc[nt].w) * rlB;
        *(float2*)&opB[c0] = ob;
    }
}

// ===========================================================================
extern "C" void kernel_launch(void* const* d_in, const int* in_sizes, int n_in,
                              void* d_out, int out_size)
{
    const float* hidden = (const float*)d_in[0];
    const float* mask   = (const float*)d_in[1];
    const float* Wq     = (const float*)d_in[2];
    const float* bq     = (const float*)d_in[3];
    const float* Wk     = (const float*)d_in[4];
    const float* bk     = (const float*)d_in[5];
    const float* Wv     = (const float*)d_in[6];
    const float* bv     = (const float*)d_in[7];
    const float* emb_k  = (const float*)d_in[8];
    const float* emb_v  = (const float*)d_in[9];
    float* out = (float*)d_out;

    dim3 g1(DD / 128, (BB * SQ) / 128, 3);
    qkv_gemm<<<g1, 256>>>(hidden, Wq, bq, Wk, bk, Wv, bv);

    dim3 g2(SQ / 16, BH);
    qrel_kernel<<<g2, 128>>>(emb_k);

    cudaFuncSetAttribute(attn_f16, cudaFuncAttributeMaxDynamicSharedMemorySize,
                         ATTN_SMEM_BYTES);
    dim3 g3(SQ / 128, BH);
    attn_f16<<<g3, 256, ATTN_SMEM_BYTES>>>(mask, emb_v, out);
}